// round 11
// baseline (speedup 1.0000x reference)
#include <cuda_runtime.h>
#include <mma.h>
#include <math.h>
using namespace nvcuda;

#define BB 4
#define TT 1024
#define MM 512
#define HH 8
#define DK 64
#define DV 64
#define NTOK (BB*TT)          // 4096
#define PROJ (HH*DK)          // 512
#define NC   (TT/64)          // 16 chunks

enum { MODE_PHI = 0, MODE_RAW = 1, MODE_VG = 2 };

// Scratch (no cudaMalloc allowed)
__device__ float g_w [5*MM*PROJ];           // tf32-rounded Wq,Wk,Wv,Wg,Wo
__device__ float g_qf[NTOK*PROJ];
__device__ float g_kf[NTOK*PROJ];
__device__ float g_v [NTOK*PROJ];
__device__ float g_o [NTOK*PROJ];
__device__ float g_ktv  [BB*HH*NC*DK*DV];
__device__ float g_state[BB*HH*NC*DK*DV];
__device__ float g_ksum [BB*HH*NC*DK];
__device__ float g_inv  [BB*HH*TT];

__device__ __forceinline__ void cp16(float* dst, const float* src) {
    unsigned d = (unsigned)__cvta_generic_to_shared(dst);
    asm volatile("cp.async.ca.shared.global [%0], [%1], 16;\n" :: "r"(d), "l"(src));
}
#define CP_COMMIT asm volatile("cp.async.commit_group;\n")
#define CP_WAIT1  asm volatile("cp.async.wait_group 1;\n")
#define CP_WAIT0  asm volatile("cp.async.wait_group 0;\n")

// ---------------------------------------------------------------------------
// Round the 5 weight matrices to tf32 (RNA) so the GEMM can cp.async them.
// ---------------------------------------------------------------------------
struct WArgs { const float* in[5]; };
__global__ __launch_bounds__(256) void preround_w(WArgs wa, float* __restrict__ out)
{
    const float* src = wa.in[blockIdx.z];
    float* dst = out + (size_t)blockIdx.z * MM * PROJ;
    int i = blockIdx.x * 256 + threadIdx.x;       // float4 index, 65536 total
    float4 x = ((const float4*)src)[i];
    x.x = wmma::__float_to_tf32(x.x); x.y = wmma::__float_to_tf32(x.y);
    x.z = wmma::__float_to_tf32(x.z); x.w = wmma::__float_to_tf32(x.w);
    ((float4*)dst)[i] = x;
}

// ---------------------------------------------------------------------------
// TF32 GEMM, two per-block modes:
//  single (PHI/RAW): BM=128, BN=128, warp tile 32x64  (Q, K, out-proj)
//  MODE_VG: dual output BM=128, BN=64 each for V and G, gate fused in epilogue
// A: raw fp32 LDG->cvt(RNA)->STS 2-deep ring. W: tf32 pre-rounded, cp.async
// 3-stage. 256 thr, 2 blocks/SM.
// ---------------------------------------------------------------------------
#define AP 36
#define ASTG (128*AP)                      // 4608 floats
#define BSTRIDE 4352                       // stage stride (fits both layouts)
#define GSMF (2*ASTG + 3*BSTRIDE)          // 22272 floats
#define GSM  (GSMF*4)                      // 89088 B

struct GemmArgs {
    const float* A[4]; const float* W[4]; const float* W2[4];
    float* C[4]; int mode[4]; int colb[4]; const float* bg;
};

__global__ __launch_bounds__(256, 2) void gemm128(GemmArgs ga)
{
    extern __shared__ float sm[];
    const int tid = threadIdx.x;
    const int z = blockIdx.z;
    const int mode = ga.mode[z];
    const float* A = ga.A[z];
    float* C = ga.C[z];
    const int wid = tid >> 5, lane = tid & 31;
    const int wr = wid >> 1, wc = wid & 1;
    const int row0 = blockIdx.y * 128;

    float* Ab[2] = { sm, sm + ASTG };
    float* Bst   = sm + 2 * ASTG;
    const int aR = tid >> 3, aC = (tid & 7) * 4;

    float4 pa[4];
    #define LOADA(kt) { \
        _Pragma("unroll") \
        for (int p = 0; p < 4; p++) \
            pa[p] = *(const float4*)(A + (size_t)(row0 + aR + p * 32) * 512 + (kt) * 32 + aC); }
    #define STSA(buf) { \
        float* As_ = Ab[buf]; \
        _Pragma("unroll") \
        for (int p = 0; p < 4; p++) { \
            float* d = As_ + (aR + p * 32) * AP + aC; \
            d[0] = wmma::__float_to_tf32(pa[p].x); d[1] = wmma::__float_to_tf32(pa[p].y); \
            d[2] = wmma::__float_to_tf32(pa[p].z); d[3] = wmma::__float_to_tf32(pa[p].w); } }

    if (mode == MODE_VG) {
        // ---- dual V/G path: BN=64 per output ----
        const float* Wv = ga.W[z]; const float* Wg2 = ga.W2[z];
        const int col0 = ga.colb[z] + blockIdx.x * 64;

        wmma::fragment<wmma::accumulator, 16, 16, 8, float> accv[2][2], accg[2][2];
        #pragma unroll
        for (int i = 0; i < 2; i++)
            #pragma unroll
            for (int j = 0; j < 2; j++) {
                wmma::fill_fragment(accv[i][j], 0.f);
                wmma::fill_fragment(accg[i][j], 0.f);
            }

        #define ISSUEB2(s, kt) { \
            float* Bs_ = Bst + (s) * BSTRIDE; \
            _Pragma("unroll") \
            for (int p = 0; p < 2; p++) { \
                int idx = tid + p * 256; \
                int r = idx >> 4, c4 = (idx & 15) * 4; \
                cp16(Bs_ + r * 68 + c4, Wv + (size_t)((kt) * 32 + r) * 512 + col0 + c4); \
                cp16(Bs_ + 2176 + r * 68 + c4, Wg2 + (size_t)((kt) * 32 + r) * 512 + col0 + c4); \
            } \
            CP_COMMIT; }

        LOADA(0); STSA(0);
        ISSUEB2(0, 0); ISSUEB2(1, 1);
        __syncthreads();
        for (int t = 0; t < 16; t++) {
            if (t < 15) { CP_WAIT1; } else { CP_WAIT0; }
            __syncthreads();
            if (t + 1 < 16) LOADA(t + 1);
            float* As_ = Ab[t & 1];
            float* Bs_ = Bst + (t % 3) * BSTRIDE;
            #pragma unroll
            for (int kk = 0; kk < 32; kk += 8) {
                wmma::fragment<wmma::matrix_a, 16, 16, 8, wmma::precision::tf32, wmma::row_major> af[2];
                wmma::fragment<wmma::matrix_b, 16, 16, 8, wmma::precision::tf32, wmma::row_major> bfv[2], bfg[2];
                #pragma unroll
                for (int i = 0; i < 2; i++)
                    wmma::load_matrix_sync(af[i], As_ + (wr * 32 + i * 16) * AP + kk, AP);
                #pragma unroll
                for (int j = 0; j < 2; j++) {
                    wmma::load_matrix_sync(bfv[j], Bs_ + kk * 68 + wc * 32 + j * 16, 68);
                    wmma::load_matrix_sync(bfg[j], Bs_ + 2176 + kk * 68 + wc * 32 + j * 16, 68);
                }
                #pragma unroll
                for (int i = 0; i < 2; i++)
                    #pragma unroll
                    for (int j = 0; j < 2; j++) {
                        wmma::mma_sync(accv[i][j], af[i], bfv[j], accv[i][j]);
                        wmma::mma_sync(accg[i][j], af[i], bfg[j], accg[i][j]);
                    }
            }
            if (t + 1 < 16) STSA((t + 1) & 1);
            if (t + 2 < 16) ISSUEB2((t + 2) % 3, t + 2);
        }
        __syncthreads();
        #undef ISSUEB2

        // epilogue: warp 32x32 strips for v and g, gate, rounded write
        float* stripV = sm + wid * 2304;
        float* stripG = stripV + 1152;
        #pragma unroll
        for (int i = 0; i < 2; i++)
            #pragma unroll
            for (int j = 0; j < 2; j++) {
                wmma::store_matrix_sync(stripV + (i * 16) * 36 + j * 16, accv[i][j], 36, wmma::mem_row_major);
                wmma::store_matrix_sync(stripG + (i * 16) * 36 + j * 16, accg[i][j], 36, wmma::mem_row_major);
            }
        __syncwarp();
        const float* bg = ga.bg;
        #pragma unroll
        for (int it = 0; it < 8; it++) {
            int e = lane + it * 32;
            int r = e >> 3, c4 = (e & 7) * 4;
            float4 v = *(float4*)(stripV + r * 36 + c4);
            float4 g = *(float4*)(stripG + r * 36 + c4);
            int gc = col0 + wc * 32 + c4;
            v.x = wmma::__float_to_tf32(v.x * (2.f / (1.f + expf(-(g.x + bg[gc + 0])))));
            v.y = wmma::__float_to_tf32(v.y * (2.f / (1.f + expf(-(g.y + bg[gc + 1])))));
            v.z = wmma::__float_to_tf32(v.z * (2.f / (1.f + expf(-(g.z + bg[gc + 2])))));
            v.w = wmma::__float_to_tf32(v.w * (2.f / (1.f + expf(-(g.w + bg[gc + 3])))));
            *(float4*)(C + (size_t)(row0 + wr * 32 + r) * 512 + gc) = v;
        }
        return;
    }

    // ---- single path: BN=128 ----
    const float* W = ga.W[z];
    const int col0 = blockIdx.x * 128;

    wmma::fragment<wmma::accumulator, 16, 16, 8, float> acc[2][4];
    #pragma unroll
    for (int i = 0; i < 2; i++)
        #pragma unroll
        for (int j = 0; j < 4; j++) wmma::fill_fragment(acc[i][j], 0.f);

    #define ISSUEB(s, kt) { \
        float* Bs_ = Bst + (s) * BSTRIDE; \
        const float* Wg_ = W + (size_t)((kt) * 32) * 512 + col0; \
        _Pragma("unroll") \
        for (int p = 0; p < 4; p++) { \
            int idx = tid + p * 256; \
            int r = idx >> 5, c4 = (idx & 31) * 4; \
            cp16(Bs_ + r * 132 + c4, Wg_ + (size_t)r * 512 + c4); \
        } \
        CP_COMMIT; }

    LOADA(0); STSA(0);
    ISSUEB(0, 0); ISSUEB(1, 1);
    __syncthreads();
    for (int t = 0; t < 16; t++) {
        if (t < 15) { CP_WAIT1; } else { CP_WAIT0; }
        __syncthreads();
        if (t + 1 < 16) LOADA(t + 1);
        float* As_ = Ab[t & 1];
        float* Bs_ = Bst + (t % 3) * BSTRIDE;
        #pragma unroll
        for (int kk = 0; kk < 32; kk += 8) {
            wmma::fragment<wmma::matrix_a, 16, 16, 8, wmma::precision::tf32, wmma::row_major> af[2];
            wmma::fragment<wmma::matrix_b, 16, 16, 8, wmma::precision::tf32, wmma::row_major> bf[4];
            #pragma unroll
            for (int i = 0; i < 2; i++)
                wmma::load_matrix_sync(af[i], As_ + (wr * 32 + i * 16) * AP + kk, AP);
            #pragma unroll
            for (int j = 0; j < 4; j++)
                wmma::load_matrix_sync(bf[j], Bs_ + kk * 132 + wc * 64 + j * 16, 132);
            #pragma unroll
            for (int i = 0; i < 2; i++)
                #pragma unroll
                for (int j = 0; j < 4; j++)
                    wmma::mma_sync(acc[i][j], af[i], bf[j], acc[i][j]);
        }
        if (t + 1 < 16) STSA((t + 1) & 1);
        if (t + 2 < 16) ISSUEB((t + 2) % 3, t + 2);
    }
    __syncthreads();
    #undef ISSUEB
    #undef LOADA
    #undef STSA

    float* strip = sm + wid * (32 * 68);
    #pragma unroll
    for (int i = 0; i < 2; i++)
        #pragma unroll
        for (int j = 0; j < 4; j++)
            wmma::store_matrix_sync(strip + (i * 16) * 68 + j * 16, acc[i][j],
                                    68, wmma::mem_row_major);
    __syncwarp();
    #pragma unroll
    for (int i2 = 0; i2 < 16; i2++) {
        int e = lane + i2 * 32;
        int r = e >> 4, c4 = (e & 15) * 4;
        float4 v = *(float4*)(strip + r * 68 + c4);
        if (mode == MODE_PHI) {
            v.x = wmma::__float_to_tf32((v.x > 0.f) ? v.x + 1.f : expf(v.x));
            v.y = wmma::__float_to_tf32((v.y > 0.f) ? v.y + 1.f : expf(v.y));
            v.z = wmma::__float_to_tf32((v.z > 0.f) ? v.z + 1.f : expf(v.z));
            v.w = wmma::__float_to_tf32((v.w > 0.f) ? v.w + 1.f : expf(v.w));
        }
        *(float4*)(C + (size_t)(row0 + wr * 32 + r) * 512 + col0 + wc * 64 + c4) = v;
    }
}

// ---------------------------------------------------------------------------
// Per-chunk K^T V (64x64) + per-chunk k column sums. grid (NC, H, B).
// ---------------------------------------------------------------------------
#define ALD 72

__global__ __launch_bounds__(256) void ktv_k(
    const float* __restrict__ kf, const float* __restrict__ vg,
    float* __restrict__ ktv, float* __restrict__ ksum)
{
    __shared__ float Kc[64 * ALD];   // [t][kd]
    __shared__ float Vc[64 * ALD];   // [t][v]
    const int c = blockIdx.x, h = blockIdx.y, b = blockIdx.z;
    const int tid = threadIdx.x;
    const int wid = tid >> 5, wr = wid >> 1, wc = wid & 1;
    const int t0 = c * 64;

    for (int e = tid; e < 64 * 16; e += 256) {
        int t = e >> 4, c4 = (e & 15) * 4;
        size_t gi = ((size_t)(b * TT + t0 + t)) * PROJ + h * DK + c4;
        *(float4*)(Kc + t * ALD + c4) = *(const float4*)(kf + gi);
        *(float4*)(Vc + t * ALD + c4) = *(const float4*)(vg + gi);
    }
    __syncthreads();

    if (tid < 64) {
        float s = 0.f;
        #pragma unroll 8
        for (int t = 0; t < 64; t++) s += Kc[t * ALD + tid];
        ksum[(((size_t)(b * HH + h)) * NC + c) * DK + tid] = s;
    }

    wmma::fragment<wmma::accumulator, 16, 16, 8, float> acc[2];
    wmma::fill_fragment(acc[0], 0.f);
    wmma::fill_fragment(acc[1], 0.f);
    #pragma unroll
    for (int kk = 0; kk < 64; kk += 8) {
        wmma::fragment<wmma::matrix_a, 16, 16, 8, wmma::precision::tf32, wmma::col_major> af;
        wmma::fragment<wmma::matrix_b, 16, 16, 8, wmma::precision::tf32, wmma::row_major> bf[2];
        wmma::load_matrix_sync(af, Kc + kk * ALD + wr * 16, ALD);
        wmma::load_matrix_sync(bf[0], Vc + kk * ALD + wc * 32, ALD);
        wmma::load_matrix_sync(bf[1], Vc + kk * ALD + wc * 32 + 16, ALD);
        wmma::mma_sync(acc[0], af, bf[0], acc[0]);
        wmma::mma_sync(acc[1], af, bf[1], acc[1]);
    }
    float* dst = ktv + (((size_t)(b * HH + h)) * NC + c) * 4096;
    wmma::store_matrix_sync(dst + (wr * 16) * 64 + wc * 32, acc[0], 64, wmma::mem_row_major);
    wmma::store_matrix_sync(dst + (wr * 16) * 64 + wc * 32 + 16, acc[1], 64, wmma::mem_row_major);
}

// ---------------------------------------------------------------------------
// Exclusive prefix over chunks -> tf32-rounded state.
// ---------------------------------------------------------------------------
__global__ __launch_bounds__(256) void state_k(
    const float* __restrict__ ktv, float* __restrict__ st)
{
    const int gid = blockIdx.x * 256 + threadIdx.x;   // 0..131071
    const int bh = gid >> 12, e = gid & 4095;
    const size_t base = ((size_t)bh * NC) * 4096 + e;
    float run = 0.f;
    #pragma unroll
    for (int c = 0; c < NC; c++) {
        st[base + c * 4096] = wmma::__float_to_tf32(run);
        run += ktv[base + c * 4096];
    }
}

// ---------------------------------------------------------------------------
// inv[t] = 1/(qf[t] . cumsum(kf)[t] + eps). grid (NC, H, B), 256 thr.
// ---------------------------------------------------------------------------
#define DLD 68
__global__ __launch_bounds__(256) void inv_k(
    const float* __restrict__ qf, const float* __restrict__ kf,
    const float* __restrict__ ksum, float* __restrict__ invd)
{
    __shared__ float Qc[64 * DLD];
    __shared__ float Kc[64 * DLD];
    __shared__ float base[64];
    const int tile = blockIdx.x, h = blockIdx.y, b = blockIdx.z;
    const int tid = threadIdx.x;
    const int bh = b * HH + h;
    const int t0 = tile * 64;

    if (tid < 64) {
        float s = 0.f;
        for (int c = 0; c < tile; c++) s += ksum[((size_t)bh * NC + c) * DK + tid];
        base[tid] = s;
    }
    for (int e = tid; e < 64 * 16; e += 256) {
        int r = e >> 4, c4 = (e & 15) * 4;
        size_t gi = ((size_t)(b * TT + t0 + r)) * PROJ + h * DK + c4;
        *(float4*)(Qc + r * DLD + c4) = *(const float4*)(qf + gi);
        *(float4*)(Kc + r * DLD + c4) = *(const float4*)(kf + gi);
    }
    __syncthreads();
    if (tid < 64) {
        float run = base[tid];
        #pragma unroll 8
        for (int r = 0; r < 64; r++) { run += Kc[r * DLD + tid]; Kc[r * DLD + tid] = run; }
    }
    __syncthreads();
    const int row = tid >> 2, seg = tid & 3;
    float d = 0.f;
    #pragma unroll
    for (int i = 0; i < 16; i++)
        d += Qc[row * DLD + seg * 16 + i] * Kc[row * DLD + seg * 16 + i];
    d += __shfl_xor_sync(0xffffffff, d, 1);
    d += __shfl_xor_sync(0xffffffff, d, 2);
    if (seg == 0) invd[(size_t)bh * TT + t0 + row] = 1.f / (d + 1e-6f);
}

// ---------------------------------------------------------------------------
// Attention: per pair (rt=p, rt=15-p). Q pre-scaled by inv.
// 3-deep K ring, one __syncthreads per column tile; Ss aliases free ring slot.
// O = Q' @ State_prev + masked(S_diag) @ V; att = S (frag-direct off-diag).
// ---------------------------------------------------------------------------
#define ATTN_SMEM ((5*64*ALD + 64) * 4)

__global__ __launch_bounds__(256) void attn_tc(
    const float* __restrict__ qf, const float* __restrict__ kf,
    const float* __restrict__ vg, const float* __restrict__ st,
    const float* __restrict__ invd,
    float* __restrict__ o, float* __restrict__ att)
{
    extern __shared__ float sm[];
    float* Qs = sm;
    float* Kb[3] = { sm + 64 * ALD, sm + 2 * 64 * ALD, sm + 3 * 64 * ALD };
    float* Vs = sm + 4 * 64 * ALD;   // state, then V
    float* inv_s = sm + 5 * 64 * ALD;

    const int tid = threadIdx.x;
    const int wid = tid >> 5, wr = wid >> 1, wc = wid & 1;
    const int pr = blockIdx.x, h = blockIdx.y, b = blockIdx.z;
    const int bh = b * HH + h;
    const size_t attBase = (size_t)bh * TT * TT;

    for (int half = 0; half < 2; half++) {
        const int rt = half ? (NC - 1 - pr) : pr;
        const int t0 = rt * 64;

        // state -> Vs (group 1)
        {
            const float* sb = st + ((size_t)bh * NC + rt) * 4096;
            #pragma unroll
            for (int p = 0; p < 4; p++) {
                int idx = tid + p * 256; int r = idx >> 4, s4 = (idx & 15) * 4;
                cp16(Vs + r * ALD + s4, sb + r * 64 + s4);
            }
        }
        CP_COMMIT;
        if (tid < 64) inv_s[tid] = invd[(size_t)bh * TT + t0 + tid];
        __syncthreads();

        // Q load + inv-scale + tf32
        #pragma unroll
        for (int p = 0; p < 4; p++) {
            int idx = tid + p * 256; int r = idx >> 4, c4 = (idx & 15) * 4;
            float4 q = *(const float4*)(qf + ((size_t)(b * TT + t0 + r)) * PROJ + h * DK + c4);
            float iv = inv_s[r];
            Qs[r * ALD + c4 + 0] = wmma::__float_to_tf32(q.x * iv);
            Qs[r * ALD + c4 + 1] = wmma::__float_to_tf32(q.y * iv);
            Qs[r * ALD + c4 + 2] = wmma::__float_to_tf32(q.z * iv);
            Qs[r * ALD + c4 + 3] = wmma::__float_to_tf32(q.w * iv);
        }
        // K(0) prefetch (group 2)
        #pragma unroll
        for (int p = 0; p < 4; p++) {
            int idx = tid + p * 256; int r = idx >> 4, s4 = (idx & 15) * 4;
            cp16(Kb[0] + r * ALD + s4, kf + ((size_t)(b * TT + r)) * PROJ + h * DK + s4);
        }
        CP_COMMIT;
        CP_WAIT1;          // state arrived (K0 may fly)
        __syncthreads();

        // acc_o = Q' @ State_prev
        wmma::fragment<wmma::accumulator, 16, 16, 8, float> acc_o[2];
        wmma::fill_fragment(acc_o[0], 0.f);
        wmma::fill_fragment(acc_o[1], 0.f);
        #pragma unroll
        for (int kk = 0; kk < 64; kk += 8) {
            wmma::fragment<wmma::matrix_a, 16, 16, 8, wmma::precision::tf32, wmma::row_major> af;
            wmma::fragment<wmma::matrix_b, 16, 16, 8, wmma::precision::tf32, wmma::row_major> bf[2];
            wmma::load_matrix_sync(af, Qs + (wr * 16) * ALD + kk, ALD);
            wmma::load_matrix_sync(bf[0], Vs + kk * ALD + wc * 32, ALD);
            wmma::load_matrix_sync(bf[1], Vs + kk * ALD + wc * 32 + 16, ALD);
            wmma::mma_sync(acc_o[0], af, bf[0], acc_o[0]);
            wmma::mma_sync(acc_o[1], af, bf[1], acc_o[1]);
        }
        __syncthreads();   // state reads done before V overwrites Vs

        for (int jt = 0; jt <= rt; jt++) {
            if (jt < rt) {
                float* dst = Kb[(jt + 1) % 3];
                const float* src = kf + ((size_t)(b * TT + (jt + 1) * 64)) * PROJ + h * DK;
                #pragma unroll
                for (int p = 0; p < 4; p++) {
                    int idx = tid + p * 256; int r = idx >> 4, s4 = (idx & 15) * 4;
                    cp16(dst + r * ALD + s4, src + (size_t)r * PROJ + s4);
                }
            } else {
                const float* src = vg + ((size_t)(b * TT + t0)) * PROJ + h * DV;
                #pragma unroll
                for (int p = 0; p < 4; p++) {
                    int idx = tid + p * 256; int r = idx >> 4, s4 = (idx & 15) * 4;
                    cp16(Vs + r * ALD + s4, src + (size_t)r * PROJ + s4);
                }
            }
            CP_COMMIT;
            CP_WAIT1;      // current K tile arrived
            __syncthreads();

            float* Kc = Kb[jt % 3];
            wmma::fragment<wmma::accumulator, 16, 16, 8, float> acc_s[2];
            wmma::fill_fragment(acc_s[0], 0.f);
            wmma::fill_fragment(acc_s[1], 0.f);
            #pragma unroll
            for (int kk = 0; kk < 64; kk += 8) {
                wmma::fragment<wmma::matrix_a, 16, 16, 8, wmma::precision::tf32, wmma::row_major> af;
                wmma::fragment<wmma::matrix_b, 16, 16, 8, wmma::precision::tf32, wmma::col_major> bf[2];
                wmma::load_matrix_sync(af, Qs + (wr * 16) * ALD + kk, ALD);
                wmma::load_matrix_sync(bf[0], Kc + (wc * 32) * ALD + kk, ALD);
                wmma::load_matrix_sync(bf[1], Kc + (wc * 32 + 16) * ALD + kk, ALD);
                wmma::mma_sync(acc_s[0], af, bf[0], acc_s[0]);
                wmma::mma_sync(acc_s[1], af, bf[1], acc_s[1]);
            }

            if (jt < rt) {
                // off-diagonal: S is the final att value — store frags direct.
                // No trailing sync: next prefetch targets Kb[(jt+2)%3], which the
                // per-iter barrier guarantees no warp is still reading.
                float* ap = att + attBase + (size_t)(t0 + wr * 16) * TT + jt * 64 + wc * 32;
                wmma::store_matrix_sync(ap, acc_s[0], TT, wmma::mem_row_major);
                wmma::store_matrix_sync(ap + 16, acc_s[1], TT, wmma::mem_row_major);
            } else {
                // diagonal: Ss aliases the free ring slot (no K(rt+1) prefetch exists)
                float* Ss = Kb[(jt + 1) % 3];
                wmma::store_matrix_sync(Ss + (wr * 16) * ALD + wc * 32, acc_s[0], ALD, wmma::mem_row_major);
                wmma::store_matrix_sync(Ss + (wr * 16) * ALD + wc * 32 + 16, acc_s[1], ALD, wmma::mem_row_major);
                CP_WAIT0;          // V arrived
                __syncthreads();
                for (int e = tid; e < 64 * 16; e += 256) {
                    int r = e >> 4, c4 = (e & 15) * 4;
                    float4 s = *(float4*)(Ss + r * ALD + c4);
                    if (c4 + 0 > r) s.x = 0.f;
                    if (c4 + 1 > r) s.y = 0.f;
                    if (c4 + 2 > r) s.z = 0.f;
                    if (c4 + 3 > r) s.w = 0.f;
                    *(float4*)(att + attBase + (size_t)(t0 + r) * TT + t0 + c4) = s;
                    Ss[r * ALD + c4 + 0] = wmma::__float_to_tf32(s.x);
                    Ss[r * ALD + c4 + 1] = wmma::__float_to_tf32(s.y);
                    Ss[r * ALD + c4 + 2] = wmma::__float_to_tf32(s.z);
                    Ss[r * ALD + c4 + 3] = wmma::__float_to_tf32(s.w);
                }
                __syncthreads();
                #pragma unroll
                for (int kk = 0; kk < 64; kk += 8) {
                    wmma::fragment<wmma::matrix_a, 16, 16, 8, wmma::precision::tf32, wmma::row_major> af;
                    wmma::fragment<wmma::matrix_b, 16, 16, 8, wmma::precision::tf32, wmma::row_major> bf[2];
                    wmma::load_matrix_sync(af, Ss + (wr * 16) * ALD + kk, ALD);
                    wmma::load_matrix_sync(bf[0], Vs + kk * ALD + wc * 32, ALD);
                    wmma::load_matrix_sync(bf[1], Vs + kk * ALD + wc * 32 + 16, ALD);
                    wmma::mma_sync(acc_o[0], af, bf[0], acc_o[0]);
                    wmma::mma_sync(acc_o[1], af, bf[1], acc_o[1]);
                }
                float* op = o + ((size_t)(b * TT + t0 + wr * 16)) * PROJ + h * DV + wc * 32;
                wmma::store_matrix_sync(op, acc_o[0], PROJ, wmma::mem_row_major);
                wmma::store_matrix_sync(op + 16, acc_o[1], PROJ, wmma::mem_row_major);
            }
        }

        // zero-fill strictly-upper tiles
        const float4 z = { 0.f, 0.f, 0.f, 0.f };
        for (int jt = rt + 1; jt < NC; jt++) {
            for (int e = tid; e < 64 * 16; e += 256) {
                int r = e >> 4, c4 = (e & 15) * 4;
                *(float4*)(att + attBase + (size_t)(t0 + r) * TT + jt * 64 + c4) = z;
            }
        }
        __syncthreads();   // smem reuse barrier for next half
    }
}

// ---------------------------------------------------------------------------
extern "C" void kernel_launch(void* const* d_in, const int* in_sizes, int n_in,
                              void* d_out, int out_size)
{
    const float* query = (const float*)d_in[0];
    const float* key   = (const float*)d_in[1];
    const float* value = (const float*)d_in[2];
    const float* Wq    = (const float*)d_in[3];
    const float* Wk    = (const float*)d_in[4];
    const float* Wv    = (const float*)d_in[5];
    const float* Wg    = (const float*)d_in[6];
    const float* bg    = (const float*)d_in[7];
    const float* Wo    = (const float*)d_in[8];

    float* out = (float*)d_out;                 // [B,T,M]
    float* att = out + (size_t)NTOK * MM;       // [B,H,T,T]

    float *w, *qf, *kf, *vg, *ov, *ktv, *st, *ksum, *invd;
    cudaGetSymbolAddress((void**)&w,  g_w);
    cudaGetSymbolAddress((void**)&qf, g_qf);
    cudaGetSymbolAddress((void**)&kf, g_kf);
    cudaGetSymbolAddress((void**)&vg, g_v);
    cudaGetSymbolAddress((void**)&ov, g_o);
    cudaGetSymbolAddress((void**)&ktv, g_ktv);
    cudaGetSymbolAddress((void**)&st, g_state);
    cudaGetSymbolAddress((void**)&ksum, g_ksum);
    cudaGetSymbolAddress((void**)&invd, g_inv);

    cudaFuncSetAttribute(gemm128, cudaFuncAttributeMaxDynamicSharedMemorySize, GSM);
    cudaFuncSetAttribute(attn_tc, cudaFuncAttributeMaxDynamicSharedMemorySize, ATTN_SMEM);

    dim3 bb(256);

    // Round weights to tf32
    WArgs wa; wa.in[0] = Wq; wa.in[1] = Wk; wa.in[2] = Wv; wa.in[3] = Wg; wa.in[4] = Wo;
    preround_w<<<dim3(256, 1, 5), bb>>>(wa, w);

    // Batched Q/K projections + fused V/gate projection
    GemmArgs p;
    p.A[0] = query; p.W[0] = w;            p.W2[0] = nullptr;      p.C[0] = qf; p.mode[0] = MODE_PHI; p.colb[0] = 0;
    p.A[1] = key;   p.W[1] = w + 262144;   p.W2[1] = nullptr;      p.C[1] = kf; p.mode[1] = MODE_PHI; p.colb[1] = 0;
    p.A[2] = value; p.W[2] = w + 2*262144; p.W2[2] = w + 3*262144; p.C[2] = vg; p.mode[2] = MODE_VG;  p.colb[2] = 0;
    p.A[3] = value; p.W[3] = w + 2*262144; p.W2[3] = w + 3*262144; p.C[3] = vg; p.mode[3] = MODE_VG;  p.colb[3] = 256;
    p.bg = bg;
    gemm128<<<dim3(4, 32, 4), bb, GSM>>>(p);

    // Per-chunk K^T V + k sums
    ktv_k<<<dim3(NC, HH, BB), bb>>>(kf, vg, ktv, ksum);

    // Exclusive state prefix
    state_k<<<512, bb>>>(ktv, st);

    // inv denominators
    inv_k<<<dim3(NC, HH, BB), bb>>>(qf, kf, ksum, invd);

    // Attention (paired row tiles)
    attn_tc<<<dim3(NC/2, HH, BB), bb, ATTN_SMEM>>>(qf, kf, vg, st, invd, ov, att);

    // Output projection
    GemmArgs po;
    po.A[0] = ov; po.W[0] = w + 4*262144; po.W2[0] = nullptr; po.C[0] = out; po.mode[0] = MODE_RAW; po.colb[0] = 0;
    po.A[1] = po.A[2] = po.A[3] = ov; po.W[1] = po.W[2] = po.W[3] = po.W[0];
    po.W2[1] = po.W2[2] = po.W2[3] = nullptr;
    po.C[1] = po.C[2] = po.C[3] = out; po.mode[1] = po.mode[2] = po.mode[3] = MODE_RAW;
    po.colb[1] = po.colb[2] = po.colb[3] = 0;
    po.bg = bg;
    gemm128<<<dim3(4, 32, 1), bb, GSM>>>(po);
}

// round 12
// speedup vs baseline: 1.0164x; 1.0164x over previous
#include <cuda_runtime.h>
#include <mma.h>
#include <math.h>
using namespace nvcuda;

#define BB 4
#define TT 1024
#define MM 512
#define HH 8
#define DK 64
#define DV 64
#define NTOK (BB*TT)          // 4096
#define PROJ (HH*DK)          // 512
#define NC   (TT/64)          // 16 chunks

enum { MODE_PHI = 0, MODE_RAW = 1 };

// Scratch (no cudaMalloc allowed)
__device__ float g_w [5*MM*PROJ];           // tf32-rounded Wq,Wk,Wv,Wg,Wo
__device__ float g_qf[NTOK*PROJ];
__device__ float g_kf[NTOK*PROJ];
__device__ float g_v [NTOK*PROJ];
__device__ float g_gt[NTOK*PROJ];
__device__ float g_o [NTOK*PROJ];
__device__ float g_ktv  [BB*HH*NC*DK*DV];
__device__ float g_state[BB*HH*NC*DK*DV];
__device__ float g_ksum [BB*HH*NC*DK];
__device__ float g_inv  [BB*HH*TT];

__device__ __forceinline__ void cp16(float* dst, const float* src) {
    unsigned d = (unsigned)__cvta_generic_to_shared(dst);
    asm volatile("cp.async.ca.shared.global [%0], [%1], 16;\n" :: "r"(d), "l"(src));
}
#define CP_COMMIT asm volatile("cp.async.commit_group;\n")
#define CP_WAIT1  asm volatile("cp.async.wait_group 1;\n")
#define CP_WAIT0  asm volatile("cp.async.wait_group 0;\n")

// ---------------------------------------------------------------------------
// Round the 5 weight matrices to tf32 (RNA) so the GEMM can cp.async them.
// ---------------------------------------------------------------------------
struct WArgs { const float* in[5]; };
__global__ __launch_bounds__(256) void preround_w(WArgs wa, float* __restrict__ out)
{
    const float* src = wa.in[blockIdx.z];
    float* dst = out + (size_t)blockIdx.z * MM * PROJ;
    int i = blockIdx.x * 256 + threadIdx.x;       // float4 index, 65536 total
    float4 x = ((const float4*)src)[i];
    x.x = wmma::__float_to_tf32(x.x); x.y = wmma::__float_to_tf32(x.y);
    x.z = wmma::__float_to_tf32(x.z); x.w = wmma::__float_to_tf32(x.w);
    ((float4*)dst)[i] = x;
}

// ---------------------------------------------------------------------------
// TF32 GEMM: C[4096,512] = A[4096,512] @ W[512,512] (+ PHI epilogue).
// BM=128, BN=128, BK=32, 256 thr (8 warps), warp tile 32x64.  (R9-measured best)
// ---------------------------------------------------------------------------
#define AP 36
#define BP 132
#define ASTG (128*AP)                      // 4608 floats
#define BSTG (32*BP)                       // 4224 floats
#define GSMF (2*ASTG + 3*BSTG)             // 21888 floats = 87552 B
#define GSM  (GSMF*4)

struct GemmArgs { const float* A[4]; const float* W[4]; float* C[4]; int mode[4]; };

__global__ __launch_bounds__(256, 2) void gemm128(GemmArgs ga)
{
    extern __shared__ float sm[];
    const int tid = threadIdx.x;
    const int z = blockIdx.z;
    const float* A = ga.A[z]; const float* W = ga.W[z];
    float* C = ga.C[z]; const int mode = ga.mode[z];

    const int wid = tid >> 5, lane = tid & 31;
    const int wr = wid >> 1, wc = wid & 1;
    const int row0 = blockIdx.y * 128, col0 = blockIdx.x * 128;

    float* Ab[2] = { sm, sm + ASTG };
    float* Bst   = sm + 2 * ASTG;

    const int aR = tid >> 3, aC = (tid & 7) * 4;
    wmma::fragment<wmma::accumulator, 16, 16, 8, float> acc[2][4];
    #pragma unroll
    for (int i = 0; i < 2; i++)
        #pragma unroll
        for (int j = 0; j < 4; j++) wmma::fill_fragment(acc[i][j], 0.f);

    float4 pa[4];
    #define LOADA(kt) { \
        _Pragma("unroll") \
        for (int p = 0; p < 4; p++) \
            pa[p] = *(const float4*)(A + (size_t)(row0 + aR + p * 32) * 512 + (kt) * 32 + aC); }
    #define STSA(buf) { \
        float* As_ = Ab[buf]; \
        _Pragma("unroll") \
        for (int p = 0; p < 4; p++) { \
            float* d = As_ + (aR + p * 32) * AP + aC; \
            d[0] = wmma::__float_to_tf32(pa[p].x); d[1] = wmma::__float_to_tf32(pa[p].y); \
            d[2] = wmma::__float_to_tf32(pa[p].z); d[3] = wmma::__float_to_tf32(pa[p].w); } }
    #define ISSUEB(s, kt) { \
        float* Bs_ = Bst + (s) * BSTG; \
        const float* Wg_ = W + (size_t)((kt) * 32) * 512 + col0; \
        _Pragma("unroll") \
        for (int p = 0; p < 4; p++) { \
            int idx = tid + p * 256; \
            int r = idx >> 5, c4 = (idx & 31) * 4; \
            cp16(Bs_ + r * BP + c4, Wg_ + (size_t)r * 512 + c4); \
        } \
        CP_COMMIT; }

    LOADA(0); STSA(0);
    ISSUEB(0, 0); ISSUEB(1, 1);
    __syncthreads();
    for (int t = 0; t < 16; t++) {
        if (t < 15) { CP_WAIT1; } else { CP_WAIT0; }
        __syncthreads();
        if (t + 1 < 16) LOADA(t + 1);
        float* As_ = Ab[t & 1];
        float* Bs_ = Bst + (t % 3) * BSTG;
        #pragma unroll
        for (int kk = 0; kk < 32; kk += 8) {
            wmma::fragment<wmma::matrix_a, 16, 16, 8, wmma::precision::tf32, wmma::row_major> af[2];
            wmma::fragment<wmma::matrix_b, 16, 16, 8, wmma::precision::tf32, wmma::row_major> bf[4];
            #pragma unroll
            for (int i = 0; i < 2; i++)
                wmma::load_matrix_sync(af[i], As_ + (wr * 32 + i * 16) * AP + kk, AP);
            #pragma unroll
            for (int j = 0; j < 4; j++)
                wmma::load_matrix_sync(bf[j], Bs_ + kk * BP + wc * 64 + j * 16, BP);
            #pragma unroll
            for (int i = 0; i < 2; i++)
                #pragma unroll
                for (int j = 0; j < 4; j++)
                    wmma::mma_sync(acc[i][j], af[i], bf[j], acc[i][j]);
        }
        if (t + 1 < 16) STSA((t + 1) & 1);
        if (t + 2 < 16) ISSUEB((t + 2) % 3, t + 2);
    }
    __syncthreads();
    #undef ISSUEB
    #undef LOADA
    #undef STSA

    float* strip = sm + wid * (32 * 68);
    #pragma unroll
    for (int i = 0; i < 2; i++)
        #pragma unroll
        for (int j = 0; j < 4; j++)
            wmma::store_matrix_sync(strip + (i * 16) * 68 + j * 16, acc[i][j],
                                    68, wmma::mem_row_major);
    __syncwarp();
    #pragma unroll
    for (int i2 = 0; i2 < 16; i2++) {
        int e = lane + i2 * 32;
        int r = e >> 4, c4 = (e & 15) * 4;
        float4 v = *(float4*)(strip + r * 68 + c4);
        if (mode == MODE_PHI) {
            v.x = wmma::__float_to_tf32((v.x > 0.f) ? v.x + 1.f : expf(v.x));
            v.y = wmma::__float_to_tf32((v.y > 0.f) ? v.y + 1.f : expf(v.y));
            v.z = wmma::__float_to_tf32((v.z > 0.f) ? v.z + 1.f : expf(v.z));
            v.w = wmma::__float_to_tf32((v.w > 0.f) ? v.w + 1.f : expf(v.w));
        }
        *(float4*)(C + (size_t)(row0 + wr * 32 + r) * 512 + col0 + wc * 64 + c4) = v;
    }
}

// ---------------------------------------------------------------------------
// Gate: vg = tf32(v * 2*sigmoid(g + bg)), elementwise in-place on g_v.
// ---------------------------------------------------------------------------
__global__ __launch_bounds__(256) void gate_k(
    float* __restrict__ v, const float* __restrict__ g, const float* __restrict__ bg)
{
    const int n4 = NTOK * PROJ / 4;
    for (int i = blockIdx.x * 256 + threadIdx.x; i < n4; i += gridDim.x * 256) {
        float4 vv = ((float4*)v)[i];
        float4 gg = ((const float4*)g)[i];
        int col = (i * 4) & 511;
        vv.x = wmma::__float_to_tf32(vv.x * (2.f / (1.f + expf(-(gg.x + bg[col + 0])))));
        vv.y = wmma::__float_to_tf32(vv.y * (2.f / (1.f + expf(-(gg.y + bg[col + 1])))));
        vv.z = wmma::__float_to_tf32(vv.z * (2.f / (1.f + expf(-(gg.z + bg[col + 2])))));
        vv.w = wmma::__float_to_tf32(vv.w * (2.f / (1.f + expf(-(gg.w + bg[col + 3])))));
        ((float4*)v)[i] = vv;
    }
}

// ---------------------------------------------------------------------------
// Per-chunk K^T V (64x64) + per-chunk k column sums. grid (NC, H, B).
// ---------------------------------------------------------------------------
#define ALD 72

__global__ __launch_bounds__(256) void ktv_k(
    const float* __restrict__ kf, const float* __restrict__ vg,
    float* __restrict__ ktv, float* __restrict__ ksum)
{
    __shared__ float Kc[64 * ALD];   // [t][kd]
    __shared__ float Vc[64 * ALD];   // [t][v]
    const int c = blockIdx.x, h = blockIdx.y, b = blockIdx.z;
    const int tid = threadIdx.x;
    const int wid = tid >> 5, wr = wid >> 1, wc = wid & 1;
    const int t0 = c * 64;

    for (int e = tid; e < 64 * 16; e += 256) {
        int t = e >> 4, c4 = (e & 15) * 4;
        size_t gi = ((size_t)(b * TT + t0 + t)) * PROJ + h * DK + c4;
        *(float4*)(Kc + t * ALD + c4) = *(const float4*)(kf + gi);
        *(float4*)(Vc + t * ALD + c4) = *(const float4*)(vg + gi);
    }
    __syncthreads();

    if (tid < 64) {
        float s = 0.f;
        #pragma unroll 8
        for (int t = 0; t < 64; t++) s += Kc[t * ALD + tid];
        ksum[(((size_t)(b * HH + h)) * NC + c) * DK + tid] = s;
    }

    wmma::fragment<wmma::accumulator, 16, 16, 8, float> acc[2];
    wmma::fill_fragment(acc[0], 0.f);
    wmma::fill_fragment(acc[1], 0.f);
    #pragma unroll
    for (int kk = 0; kk < 64; kk += 8) {
        wmma::fragment<wmma::matrix_a, 16, 16, 8, wmma::precision::tf32, wmma::col_major> af;
        wmma::fragment<wmma::matrix_b, 16, 16, 8, wmma::precision::tf32, wmma::row_major> bf[2];
        wmma::load_matrix_sync(af, Kc + kk * ALD + wr * 16, ALD);
        wmma::load_matrix_sync(bf[0], Vc + kk * ALD + wc * 32, ALD);
        wmma::load_matrix_sync(bf[1], Vc + kk * ALD + wc * 32 + 16, ALD);
        wmma::mma_sync(acc[0], af, bf[0], acc[0]);
        wmma::mma_sync(acc[1], af, bf[1], acc[1]);
    }
    float* dst = ktv + (((size_t)(b * HH + h)) * NC + c) * 4096;
    wmma::store_matrix_sync(dst + (wr * 16) * 64 + wc * 32, acc[0], 64, wmma::mem_row_major);
    wmma::store_matrix_sync(dst + (wr * 16) * 64 + wc * 32 + 16, acc[1], 64, wmma::mem_row_major);
}

// ---------------------------------------------------------------------------
// Exclusive prefix over chunks -> tf32-rounded state.
// ---------------------------------------------------------------------------
__global__ __launch_bounds__(256) void state_k(
    const float* __restrict__ ktv, float* __restrict__ st)
{
    const int gid = blockIdx.x * 256 + threadIdx.x;   // 0..131071
    const int bh = gid >> 12, e = gid & 4095;
    const size_t base = ((size_t)bh * NC) * 4096 + e;
    float run = 0.f;
    #pragma unroll
    for (int c = 0; c < NC; c++) {
        st[base + c * 4096] = wmma::__float_to_tf32(run);
        run += ktv[base + c * 4096];
    }
}

// ---------------------------------------------------------------------------
// inv[t] = 1/(qf[t] . cumsum(kf)[t] + eps). grid (NC, H, B), 256 thr.
// ---------------------------------------------------------------------------
#define DLD 68
__global__ __launch_bounds__(256) void inv_k(
    const float* __restrict__ qf, const float* __restrict__ kf,
    const float* __restrict__ ksum, float* __restrict__ invd)
{
    __shared__ float Qc[64 * DLD];
    __shared__ float Kc[64 * DLD];
    __shared__ float base[64];
    const int tile = blockIdx.x, h = blockIdx.y, b = blockIdx.z;
    const int tid = threadIdx.x;
    const int bh = b * HH + h;
    const int t0 = tile * 64;

    if (tid < 64) {
        float s = 0.f;
        for (int c = 0; c < tile; c++) s += ksum[((size_t)bh * NC + c) * DK + tid];
        base[tid] = s;
    }
    for (int e = tid; e < 64 * 16; e += 256) {
        int r = e >> 4, c4 = (e & 15) * 4;
        size_t gi = ((size_t)(b * TT + t0 + r)) * PROJ + h * DK + c4;
        *(float4*)(Qc + r * DLD + c4) = *(const float4*)(qf + gi);
        *(float4*)(Kc + r * DLD + c4) = *(const float4*)(kf + gi);
    }
    __syncthreads();
    if (tid < 64) {
        float run = base[tid];
        #pragma unroll 8
        for (int r = 0; r < 64; r++) { run += Kc[r * DLD + tid]; Kc[r * DLD + tid] = run; }
    }
    __syncthreads();
    const int row = tid >> 2, seg = tid & 3;
    float d = 0.f;
    #pragma unroll
    for (int i = 0; i < 16; i++)
        d += Qc[row * DLD + seg * 16 + i] * Kc[row * DLD + seg * 16 + i];
    d += __shfl_xor_sync(0xffffffff, d, 1);
    d += __shfl_xor_sync(0xffffffff, d, 2);
    if (seg == 0) invd[(size_t)bh * TT + t0 + row] = 1.f / (d + 1e-6f);
}

// ---------------------------------------------------------------------------
// Attention, 128-row Q tiles. Per (b,h) pair (rb=pr, rb=7-pr): 18 tiles each.
// Q pre-scaled by inv. Upper half (chunk c0=2rb) uses state[c0]; lower half
// (chunk c1) uses state[c1]. Diagonal 128x128 block = two masked 64-steps;
// lower half at column c0 is a FULL tile (contribution already in state[c1]).
// ---------------------------------------------------------------------------
#define ATTN_SMEM ((128*ALD + 6*64*ALD + 128) * 4)   // 147968 B

__global__ __launch_bounds__(256) void attn_tc(
    const float* __restrict__ qf, const float* __restrict__ kf,
    const float* __restrict__ vg, const float* __restrict__ st,
    const float* __restrict__ invd,
    float* __restrict__ o, float* __restrict__ att)
{
    extern __shared__ float sm[];
    float* Qs  = sm;                               // 128 x ALD
    float* Kb[3] = { sm + 128*ALD, sm + 128*ALD + 64*ALD, sm + 128*ALD + 2*64*ALD };
    float* SV0 = sm + 128*ALD + 3*64*ALD;          // state[c0] then V[c0]
    float* SV1 = SV0 + 64*ALD;                     // state[c1] then V[c1]
    float* Ss  = SV1 + 64*ALD;                     // diag staging
    float* inv_s = Ss + 64*ALD;                    // 128

    const int tid = threadIdx.x;
    const int wid = tid >> 5, wr = wid >> 1, wc = wid & 1;   // 4x2 warps: 32x32 tiles
    const int pr = blockIdx.x, h = blockIdx.y, b = blockIdx.z;
    const int bh = b * HH + h;
    const size_t attBase = (size_t)bh * TT * TT;

    for (int half = 0; half < 2; half++) {
        const int rb = half ? (7 - pr) : pr;
        const int c0 = 2 * rb, c1 = 2 * rb + 1;
        const int t0 = rb * 128;

        // states -> SV0/SV1 (group 1)
        {
            const float* s0 = st + ((size_t)bh * NC + c0) * 4096;
            const float* s1 = st + ((size_t)bh * NC + c1) * 4096;
            #pragma unroll
            for (int p = 0; p < 4; p++) {
                int idx = tid + p * 256; int r = idx >> 4, s4 = (idx & 15) * 4;
                cp16(SV0 + r * ALD + s4, s0 + r * 64 + s4);
                cp16(SV1 + r * ALD + s4, s1 + r * 64 + s4);
            }
        }
        CP_COMMIT;
        if (tid < 128) inv_s[tid] = invd[(size_t)bh * TT + t0 + tid];
        __syncthreads();

        // Q (128x64) load + inv-scale + tf32
        #pragma unroll
        for (int p = 0; p < 8; p++) {
            int idx = tid + p * 256; int r = idx >> 4, c4 = (idx & 15) * 4;
            float4 q = *(const float4*)(qf + ((size_t)(b * TT + t0 + r)) * PROJ + h * DK + c4);
            float iv = inv_s[r];
            Qs[r * ALD + c4 + 0] = wmma::__float_to_tf32(q.x * iv);
            Qs[r * ALD + c4 + 1] = wmma::__float_to_tf32(q.y * iv);
            Qs[r * ALD + c4 + 2] = wmma::__float_to_tf32(q.z * iv);
            Qs[r * ALD + c4 + 3] = wmma::__float_to_tf32(q.w * iv);
        }
        // K(0) prefetch (group 2)
        #pragma unroll
        for (int p = 0; p < 4; p++) {
            int idx = tid + p * 256; int r = idx >> 4, s4 = (idx & 15) * 4;
            cp16(Kb[0] + r * ALD + s4, kf + ((size_t)(b * TT + r)) * PROJ + h * DK + s4);
        }
        CP_COMMIT;
        CP_WAIT1;          // states arrived
        __syncthreads();

        // acc_o = Q' @ state (upper warps state[c0], lower state[c1])
        wmma::fragment<wmma::accumulator, 16, 16, 8, float> acc_o[2][2];
        #pragma unroll
        for (int i = 0; i < 2; i++)
            #pragma unroll
            for (int j = 0; j < 2; j++) wmma::fill_fragment(acc_o[i][j], 0.f);
        {
            float* stw = (wr < 2) ? SV0 : SV1;
            #pragma unroll
            for (int kk = 0; kk < 64; kk += 8) {
                wmma::fragment<wmma::matrix_a, 16, 16, 8, wmma::precision::tf32, wmma::row_major> af[2];
                wmma::fragment<wmma::matrix_b, 16, 16, 8, wmma::precision::tf32, wmma::row_major> bf[2];
                #pragma unroll
                for (int i = 0; i < 2; i++)
                    wmma::load_matrix_sync(af[i], Qs + (wr * 32 + i * 16) * ALD + kk, ALD);
                #pragma unroll
                for (int j = 0; j < 2; j++)
                    wmma::load_matrix_sync(bf[j], stw + kk * ALD + wc * 32 + j * 16, ALD);
                #pragma unroll
                for (int i = 0; i < 2; i++)
                    #pragma unroll
                    for (int j = 0; j < 2; j++)
                        wmma::mma_sync(acc_o[i][j], af[i], bf[j], acc_o[i][j]);
            }
        }
        __syncthreads();   // state reads done; SV0/SV1 reusable for V

        for (int jt = 0; jt <= c1; jt++) {
            // issue exactly one cp.async group per iteration
            if (jt < c0) {
                float* dst = Kb[(jt + 1) % 3];
                const float* src = kf + ((size_t)(b * TT + (jt + 1) * 64)) * PROJ + h * DK;
                #pragma unroll
                for (int p = 0; p < 4; p++) {
                    int idx = tid + p * 256; int r = idx >> 4, s4 = (idx & 15) * 4;
                    cp16(dst + r * ALD + s4, src + (size_t)r * PROJ + s4);
                }
            } else if (jt == c0) {
                float* dst = Kb[c1 % 3];
                const float* srcK = kf + ((size_t)(b * TT + c1 * 64)) * PROJ + h * DK;
                const float* srcV = vg + ((size_t)(b * TT + t0)) * PROJ + h * DV;
                #pragma unroll
                for (int p = 0; p < 4; p++) {
                    int idx = tid + p * 256; int r = idx >> 4, s4 = (idx & 15) * 4;
                    cp16(dst + r * ALD + s4, srcK + (size_t)r * PROJ + s4);
                    cp16(SV0 + r * ALD + s4, srcV + (size_t)r * PROJ + s4);
                }
            } else { // jt == c1: V1
                const float* srcV = vg + ((size_t)(b * TT + t0 + 64)) * PROJ + h * DV;
                #pragma unroll
                for (int p = 0; p < 4; p++) {
                    int idx = tid + p * 256; int r = idx >> 4, s4 = (idx & 15) * 4;
                    cp16(SV1 + r * ALD + s4, srcV + (size_t)r * PROJ + s4);
                }
            }
            CP_COMMIT;
            CP_WAIT1;      // current K tile arrived
            __syncthreads();

            float* Kc = Kb[jt % 3];

            if (jt < c1) {
                // S (128x64) = Q' @ K^T : warp 32x32, 4 frags
                wmma::fragment<wmma::accumulator, 16, 16, 8, float> acc_s[2][2];
                #pragma unroll
                for (int i = 0; i < 2; i++)
                    #pragma unroll
                    for (int j = 0; j < 2; j++) wmma::fill_fragment(acc_s[i][j], 0.f);
                #pragma unroll
                for (int kk = 0; kk < 64; kk += 8) {
                    wmma::fragment<wmma::matrix_a, 16, 16, 8, wmma::precision::tf32, wmma::row_major> af[2];
                    wmma::fragment<wmma::matrix_b, 16, 16, 8, wmma::precision::tf32, wmma::col_major> bf[2];
                    #pragma unroll
                    for (int i = 0; i < 2; i++)
                        wmma::load_matrix_sync(af[i], Qs + (wr * 32 + i * 16) * ALD + kk, ALD);
                    #pragma unroll
                    for (int j = 0; j < 2; j++)
                        wmma::load_matrix_sync(bf[j], Kc + (wc * 32 + j * 16) * ALD + kk, ALD);
                    #pragma unroll
                    for (int i = 0; i < 2; i++)
                        #pragma unroll
                        for (int j = 0; j < 2; j++)
                            wmma::mma_sync(acc_s[i][j], af[i], bf[j], acc_s[i][j]);
                }

                if (jt < c0 || wr >= 2) {
                    // full rows: S is final att — store frags direct
                    #pragma unroll
                    for (int i = 0; i < 2; i++)
                        #pragma unroll
                        for (int j = 0; j < 2; j++)
                            wmma::store_matrix_sync(
                                att + attBase + (size_t)(t0 + wr * 32 + i * 16) * TT
                                    + jt * 64 + wc * 32 + j * 16,
                                acc_s[i][j], TT, wmma::mem_row_major);
                } else {
                    // upper-diag rows (jt==c0, wr<2): stage to Ss
                    #pragma unroll
                    for (int i = 0; i < 2; i++)
                        #pragma unroll
                        for (int j = 0; j < 2; j++)
                            wmma::store_matrix_sync(
                                Ss + (wr * 32 + i * 16) * ALD + wc * 32 + j * 16,
                                acc_s[i][j], ALD, wmma::mem_row_major);
                }

                if (jt == c0) {
                    // diagonal (upper 64 rows): mask, att write, tf32, S@V0
                    CP_WAIT0;          // K(c1) + V0 arrived
                    __syncthreads();
                    for (int e = tid; e < 64 * 16; e += 256) {
                        int r = e >> 4, c4 = (e & 15) * 4;
                        float4 s = *(float4*)(Ss + r * ALD + c4);
                        if (c4 + 0 > r) s.x = 0.f;
                        if (c4 + 1 > r) s.y = 0.f;
                        if (c4 + 2 > r) s.z = 0.f;
                        if (c4 + 3 > r) s.w = 0.f;
                        *(float4*)(att + attBase + (size_t)(t0 + r) * TT + t0 + c4) = s;
                        Ss[r * ALD + c4 + 0] = wmma::__float_to_tf32(s.x);
                        Ss[r * ALD + c4 + 1] = wmma::__float_to_tf32(s.y);
                        Ss[r * ALD + c4 + 2] = wmma::__float_to_tf32(s.z);
                        Ss[r * ALD + c4 + 3] = wmma::__float_to_tf32(s.w);
                    }
                    __syncthreads();
                    if (wr < 2) {
                        #pragma unroll
                        for (int kk = 0; kk < 64; kk += 8) {
                            wmma::fragment<wmma::matrix_a, 16, 16, 8, wmma::precision::tf32, wmma::row_major> af[2];
                            wmma::fragment<wmma::matrix_b, 16, 16, 8, wmma::precision::tf32, wmma::row_major> bf[2];
                            #pragma unroll
                            for (int i = 0; i < 2; i++)
                                wmma::load_matrix_sync(af[i], Ss + (wr * 32 + i * 16) * ALD + kk, ALD);
                            #pragma unroll
                            for (int j = 0; j < 2; j++)
                                wmma::load_matrix_sync(bf[j], SV0 + kk * ALD + wc * 32 + j * 16, ALD);
                            #pragma unroll
                            for (int i = 0; i < 2; i++)
                                #pragma unroll
                                for (int j = 0; j < 2; j++)
                                    wmma::mma_sync(acc_o[i][j], af[i], bf[j], acc_o[i][j]);
                        }
                    }
                }
            } else {
                // jt == c1: lower-diag 64x64 (rows t0+64..t0+127), lower warps only
                if (wr >= 2) {
                    wmma::fragment<wmma::accumulator, 16, 16, 8, float> acc_s[2][2];
                    #pragma unroll
                    for (int i = 0; i < 2; i++)
                        #pragma unroll
                        for (int j = 0; j < 2; j++) wmma::fill_fragment(acc_s[i][j], 0.f);
                    const int lr = (wr - 2) * 32;   // local row band in 64-row tile
                    #pragma unroll
                    for (int kk = 0; kk < 64; kk += 8) {
                        wmma::fragment<wmma::matrix_a, 16, 16, 8, wmma::precision::tf32, wmma::row_major> af[2];
                        wmma::fragment<wmma::matrix_b, 16, 16, 8, wmma::precision::tf32, wmma::col_major> bf[2];
                        #pragma unroll
                        for (int i = 0; i < 2; i++)
                            wmma::load_matrix_sync(af[i], Qs + (64 + lr + i * 16) * ALD + kk, ALD);
                        #pragma unroll
                        for (int j = 0; j < 2; j++)
                            wmma::load_matrix_sync(bf[j], Kc + (wc * 32 + j * 16) * ALD + kk, ALD);
                        #pragma unroll
                        for (int i = 0; i < 2; i++)
                            #pragma unroll
                            for (int j = 0; j < 2; j++)
                                wmma::mma_sync(acc_s[i][j], af[i], bf[j], acc_s[i][j]);
                    }
                    #pragma unroll
                    for (int i = 0; i < 2; i++)
                        #pragma unroll
                        for (int j = 0; j < 2; j++)
                            wmma::store_matrix_sync(
                                Ss + (lr + i * 16) * ALD + wc * 32 + j * 16,
                                acc_s[i][j], ALD, wmma::mem_row_major);
                }
                CP_WAIT0;          // V1 arrived
                __syncthreads();
                for (int e = tid; e < 64 * 16; e += 256) {
                    int r = e >> 4, c4 = (e & 15) * 4;
                    float4 s = *(float4*)(Ss + r * ALD + c4);
                    if (c4 + 0 > r) s.x = 0.f;
                    if (c4 + 1 > r) s.y = 0.f;
                    if (c4 + 2 > r) s.z = 0.f;
                    if (c4 + 3 > r) s.w = 0.f;
                    *(float4*)(att + attBase + (size_t)(t0 + 64 + r) * TT + t0 + 64 + c4) = s;
                    Ss[r * ALD + c4 + 0] = wmma::__float_to_tf32(s.x);
                    Ss[r * ALD + c4 + 1] = wmma::__float_to_tf32(s.y);
                    Ss[r * ALD + c4 + 2] = wmma::__float_to_tf32(s.z);
                    Ss[r * ALD + c4 + 3] = wmma::__float_to_tf32(s.w);
                }
                __syncthreads();
                if (wr >= 2) {
                    const int lr = (wr - 2) * 32;
                    #pragma unroll
                    for (int kk = 0; kk < 64; kk += 8) {
                        wmma::fragment<wmma::matrix_a, 16, 16, 8, wmma::precision::tf32, wmma::row_major> af[2];
                        wmma::fragment<wmma::matrix_b, 16, 16, 8, wmma::precision::tf32, wmma::row_major> bf[2];
                        #pragma unroll
                        for (int i = 0; i < 2; i++)
                            wmma::load_matrix_sync(af[i], Ss + (lr + i * 16) * ALD + kk, ALD);
                        #pragma unroll
                        for (int j = 0; j < 2; j++)
                            wmma::load_matrix_sync(bf[j], SV1 + kk * ALD + wc * 32 + j * 16, ALD);
                        #pragma unroll
                        for (int i = 0; i < 2; i++)
                            #pragma unroll
                            for (int j = 0; j < 2; j++)
                                wmma::mma_sync(acc_o[i][j], af[i], bf[j], acc_o[i][j]);
                    }
                }
            }
        }

        // O store (raw fp32 frags; out-proj rounds its own A)
        #pragma unroll
        for (int i = 0; i < 2; i++)
            #pragma unroll
            for (int j = 0; j < 2; j++)
                wmma::store_matrix_sync(
                    o + ((size_t)(b * TT + t0 + wr * 32 + i * 16)) * PROJ
                        + h * DV + wc * 32 + j * 16,
                    acc_o[i][j], PROJ, wmma::mem_row_major);

        // zero-fill strictly-upper tiles
        const float4 z = { 0.f, 0.f, 0.f, 0.f };
        for (int jt = c0 + 1; jt < NC; jt++)
            for (int e = tid; e < 64 * 16; e += 256) {
                int r = e >> 4, c4 = (e & 15) * 4;
                *(float4*)(att + attBase + (size_t)(t0 + r) * TT + jt * 64 + c4) = z;
            }
        for (int jt = c1 + 1; jt < NC; jt++)
            for (int e = tid; e < 64 * 16; e += 256) {
                int r = e >> 4, c4 = (e & 15) * 4;
                *(float4*)(att + attBase + (size_t)(t0 + 64 + r) * TT + jt * 64 + c4) = z;
            }
        __syncthreads();   // smem reuse barrier for next half
    }
}

// ---------------------------------------------------------------------------
extern "C" void kernel_launch(void* const* d_in, const int* in_sizes, int n_in,
                              void* d_out, int out_size)
{
    const float* query = (const float*)d_in[0];
    const float* key   = (const float*)d_in[1];
    const float* value = (const float*)d_in[2];
    const float* Wq    = (const float*)d_in[3];
    const float* Wk    = (const float*)d_in[4];
    const float* Wv    = (const float*)d_in[5];
    const float* Wg    = (const float*)d_in[6];
    const float* bg    = (const float*)d_in[7];
    const float* Wo    = (const float*)d_in[8];

    float* out = (float*)d_out;                 // [B,T,M]
    float* att = out + (size_t)NTOK * MM;       // [B,H,T,T]

    float *w, *qf, *kf, *vg, *gt, *ov, *ktv, *st, *ksum, *invd;
    cudaGetSymbolAddress((void**)&w,  g_w);
    cudaGetSymbolAddress((void**)&qf, g_qf);
    cudaGetSymbolAddress((void**)&kf, g_kf);
    cudaGetSymbolAddress((void**)&vg, g_v);
    cudaGetSymbolAddress((void**)&gt, g_gt);
    cudaGetSymbolAddress((void**)&ov, g_o);
    cudaGetSymbolAddress((void**)&ktv, g_ktv);
    cudaGetSymbolAddress((void**)&st, g_state);
    cudaGetSymbolAddress((void**)&ksum, g_ksum);
    cudaGetSymbolAddress((void**)&invd, g_inv);

    cudaFuncSetAttribute(gemm128, cudaFuncAttributeMaxDynamicSharedMemorySize, GSM);
    cudaFuncSetAttribute(attn_tc, cudaFuncAttributeMaxDynamicSharedMemorySize, ATTN_SMEM);

    dim3 bb(256);

    // Round weights to tf32
    WArgs wa; wa.in[0] = Wq; wa.in[1] = Wk; wa.in[2] = Wv; wa.in[3] = Wg; wa.in[4] = Wo;
    preround_w<<<dim3(256, 1, 5), bb>>>(wa, w);

    // Batched Q/K/V/gate projections (A conversion folded into GEMM)
    GemmArgs p;
    p.A[0] = query; p.W[0] = w;            p.C[0] = qf; p.mode[0] = MODE_PHI;
    p.A[1] = key;   p.W[1] = w + 262144;   p.C[1] = kf; p.mode[1] = MODE_PHI;
    p.A[2] = value; p.W[2] = w + 2*262144; p.C[2] = vg; p.mode[2] = MODE_RAW;
    p.A[3] = value; p.W[3] = w + 3*262144; p.C[3] = gt; p.mode[3] = MODE_RAW;
    gemm128<<<dim3(4, 32, 4), bb, GSM>>>(p);

    // Gate (in place on vg), tf32-rounded
    gate_k<<<1024, bb>>>(vg, gt, bg);

    // Per-chunk K^T V + k sums
    ktv_k<<<dim3(NC, HH, BB), bb>>>(kf, vg, ktv, ksum);

    // Exclusive state prefix
    state_k<<<512, bb>>>(ktv, st);

    // inv denominators
    inv_k<<<dim3(NC, HH, BB), bb>>>(qf, kf, ksum, invd);

    // Attention: 128-row tiles, paired row-blocks (rb, 7-rb)
    attn_tc<<<dim3(4, HH, BB), bb, ATTN_SMEM>>>(qf, kf, vg, st, invd, ov, att);

    // Output projection
    GemmArgs po;
    po.A[0] = ov; po.W[0] = w + 4*262144; po.C[0] = out; po.mode[0] = MODE_RAW;
    po.A[1] = po.A[2] = po.A[3] = ov; po.W[1] = po.W[2] = po.W[3] = po.W[0];
    po.C[1] = po.C[2] = po.C[3] = out; po.mode[1] = po.mode[2] = po.mode[3] = MODE_RAW;
    gemm128<<<dim3(4, 32, 1), bb, GSM>>>(po);
}

// round 15
// speedup vs baseline: 1.0237x; 1.0072x over previous
#include <cuda_runtime.h>
#include <mma.h>
#include <math.h>
using namespace nvcuda;

#define BB 4
#define TT 1024
#define MM 512
#define HH 8
#define DK 64
#define DV 64
#define NTOK (BB*TT)          // 4096
#define PROJ (HH*DK)          // 512
#define NC   (TT/64)          // 16 chunks

enum { MODE_PHI = 0, MODE_RAW = 1 };

// Scratch (no cudaMalloc allowed)
__device__ float g_w [5*MM*PROJ];           // tf32-rounded Wq,Wk,Wv,Wg,Wo
__device__ float g_qf[NTOK*PROJ];
__device__ float g_kf[NTOK*PROJ];
__device__ float g_v [NTOK*PROJ];
__device__ float g_gt[NTOK*PROJ];
__device__ float g_o [NTOK*PROJ];
__device__ float g_ktv  [BB*HH*NC*DK*DV];
__device__ float g_state[BB*HH*NC*DK*DV];
__device__ float g_ksum [BB*HH*NC*DK];
__device__ float g_inv  [BB*HH*TT];

__device__ __forceinline__ void cp16(float* dst, const float* src) {
    unsigned d = (unsigned)__cvta_generic_to_shared(dst);
    asm volatile("cp.async.ca.shared.global [%0], [%1], 16;\n" :: "r"(d), "l"(src));
}
#define CP_COMMIT asm volatile("cp.async.commit_group;\n")
#define CP_WAIT1  asm volatile("cp.async.wait_group 1;\n")
#define CP_WAIT0  asm volatile("cp.async.wait_group 0;\n")

// ---------------------------------------------------------------------------
// Round the 5 weight matrices to tf32 (RNA) so the GEMM can cp.async them.
// ---------------------------------------------------------------------------
struct WArgs { const float* in[5]; };
__global__ __launch_bounds__(256) void preround_w(WArgs wa, float* __restrict__ out)
{
    const float* src = wa.in[blockIdx.z];
    float* dst = out + (size_t)blockIdx.z * MM * PROJ;
    int i = blockIdx.x * 256 + threadIdx.x;       // float4 index, 65536 total
    float4 x = ((const float4*)src)[i];
    x.x = wmma::__float_to_tf32(x.x); x.y = wmma::__float_to_tf32(x.y);
    x.z = wmma::__float_to_tf32(x.z); x.w = wmma::__float_to_tf32(x.w);
    ((float4*)dst)[i] = x;
}

// ---------------------------------------------------------------------------
// TF32 GEMM: C[4096,512] = A[4096,512] @ W[512,512] (+ PHI epilogue).
// BM=128, BN=128, BK=32, 256 thr (8 warps), warp tile 32x64.  (R9-measured best)
// ---------------------------------------------------------------------------
#define AP 36
#define BP 132
#define ASTG (128*AP)                      // 4608 floats
#define BSTG (32*BP)                       // 4224 floats
#define GSMF (2*ASTG + 3*BSTG)             // 21888 floats = 87552 B
#define GSM  (GSMF*4)

struct GemmArgs { const float* A[4]; const float* W[4]; float* C[4]; int mode[4]; };

__global__ __launch_bounds__(256, 2) void gemm128(GemmArgs ga)
{
    extern __shared__ float sm[];
    const int tid = threadIdx.x;
    const int z = blockIdx.z;
    const float* A = ga.A[z]; const float* W = ga.W[z];
    float* C = ga.C[z]; const int mode = ga.mode[z];

    const int wid = tid >> 5, lane = tid & 31;
    const int wr = wid >> 1, wc = wid & 1;
    const int row0 = blockIdx.y * 128, col0 = blockIdx.x * 128;

    float* Ab[2] = { sm, sm + ASTG };
    float* Bst   = sm + 2 * ASTG;

    const int aR = tid >> 3, aC = (tid & 7) * 4;
    wmma::fragment<wmma::accumulator, 16, 16, 8, float> acc[2][4];
    #pragma unroll
    for (int i = 0; i < 2; i++)
        #pragma unroll
        for (int j = 0; j < 4; j++) wmma::fill_fragment(acc[i][j], 0.f);

    float4 pa[4];
    #define LOADA(kt) { \
        _Pragma("unroll") \
        for (int p = 0; p < 4; p++) \
            pa[p] = *(const float4*)(A + (size_t)(row0 + aR + p * 32) * 512 + (kt) * 32 + aC); }
    #define STSA(buf) { \
        float* As_ = Ab[buf]; \
        _Pragma("unroll") \
        for (int p = 0; p < 4; p++) { \
            float* d = As_ + (aR + p * 32) * AP + aC; \
            d[0] = wmma::__float_to_tf32(pa[p].x); d[1] = wmma::__float_to_tf32(pa[p].y); \
            d[2] = wmma::__float_to_tf32(pa[p].z); d[3] = wmma::__float_to_tf32(pa[p].w); } }
    #define ISSUEB(s, kt) { \
        float* Bs_ = Bst + (s) * BSTG; \
        const float* Wg_ = W + (size_t)((kt) * 32) * 512 + col0; \
        _Pragma("unroll") \
        for (int p = 0; p < 4; p++) { \
            int idx = tid + p * 256; \
            int r = idx >> 5, c4 = (idx & 31) * 4; \
            cp16(Bs_ + r * BP + c4, Wg_ + (size_t)r * 512 + c4); \
        } \
        CP_COMMIT; }

    LOADA(0); STSA(0);
    ISSUEB(0, 0); ISSUEB(1, 1);
    __syncthreads();
    for (int t = 0; t < 16; t++) {
        if (t < 15) { CP_WAIT1; } else { CP_WAIT0; }
        __syncthreads();
        if (t + 1 < 16) LOADA(t + 1);
        float* As_ = Ab[t & 1];
        float* Bs_ = Bst + (t % 3) * BSTG;
        #pragma unroll
        for (int kk = 0; kk < 32; kk += 8) {
            wmma::fragment<wmma::matrix_a, 16, 16, 8, wmma::precision::tf32, wmma::row_major> af[2];
            wmma::fragment<wmma::matrix_b, 16, 16, 8, wmma::precision::tf32, wmma::row_major> bf[4];
            #pragma unroll
            for (int i = 0; i < 2; i++)
                wmma::load_matrix_sync(af[i], As_ + (wr * 32 + i * 16) * AP + kk, AP);
            #pragma unroll
            for (int j = 0; j < 4; j++)
                wmma::load_matrix_sync(bf[j], Bs_ + kk * BP + wc * 64 + j * 16, BP);
            #pragma unroll
            for (int i = 0; i < 2; i++)
                #pragma unroll
                for (int j = 0; j < 4; j++)
                    wmma::mma_sync(acc[i][j], af[i], bf[j], acc[i][j]);
        }
        if (t + 1 < 16) STSA((t + 1) & 1);
        if (t + 2 < 16) ISSUEB((t + 2) % 3, t + 2);
    }
    __syncthreads();
    #undef ISSUEB
    #undef LOADA
    #undef STSA

    float* strip = sm + wid * (32 * 68);
    #pragma unroll
    for (int i = 0; i < 2; i++)
        #pragma unroll
        for (int j = 0; j < 4; j++)
            wmma::store_matrix_sync(strip + (i * 16) * 68 + j * 16, acc[i][j],
                                    68, wmma::mem_row_major);
    __syncwarp();
    #pragma unroll
    for (int i2 = 0; i2 < 16; i2++) {
        int e = lane + i2 * 32;
        int r = e >> 4, c4 = (e & 15) * 4;
        float4 v = *(float4*)(strip + r * 68 + c4);
        if (mode == MODE_PHI) {
            v.x = wmma::__float_to_tf32((v.x > 0.f) ? v.x + 1.f : expf(v.x));
            v.y = wmma::__float_to_tf32((v.y > 0.f) ? v.y + 1.f : expf(v.y));
            v.z = wmma::__float_to_tf32((v.z > 0.f) ? v.z + 1.f : expf(v.z));
            v.w = wmma::__float_to_tf32((v.w > 0.f) ? v.w + 1.f : expf(v.w));
        }
        *(float4*)(C + (size_t)(row0 + wr * 32 + r) * 512 + col0 + wc * 64 + c4) = v;
    }
}

// ---------------------------------------------------------------------------
// Fused gate + per-chunk K^T V + per-chunk k column sums. grid (NC, H, B).
// Gates raw v with gt in registers (identical formula/rounding to old gate_k),
// writes gated vg back to gmem, and uses it for the K^T V mma.
// ---------------------------------------------------------------------------
#define ALD 72

__global__ __launch_bounds__(256) void ktv_k(
    const float* __restrict__ kf, float* __restrict__ vg,
    const float* __restrict__ gt, const float* __restrict__ bg,
    float* __restrict__ ktv, float* __restrict__ ksum)
{
    __shared__ float Kc[64 * ALD];   // [t][kd]
    __shared__ float Vc[64 * ALD];   // [t][v] (gated)
    const int c = blockIdx.x, h = blockIdx.y, b = blockIdx.z;
    const int tid = threadIdx.x;
    const int wid = tid >> 5, wr = wid >> 1, wc = wid & 1;
    const int t0 = c * 64;

    for (int e = tid; e < 64 * 16; e += 256) {
        int t = e >> 4, c4 = (e & 15) * 4;
        size_t gi = ((size_t)(b * TT + t0 + t)) * PROJ + h * DK + c4;
        *(float4*)(Kc + t * ALD + c4) = *(const float4*)(kf + gi);
        float4 vv = *(const float4*)(vg + gi);
        float4 gg = *(const float4*)(gt + gi);
        int col = h * DV + c4;
        vv.x = wmma::__float_to_tf32(vv.x * (2.f / (1.f + expf(-(gg.x + bg[col + 0])))));
        vv.y = wmma::__float_to_tf32(vv.y * (2.f / (1.f + expf(-(gg.y + bg[col + 1])))));
        vv.z = wmma::__float_to_tf32(vv.z * (2.f / (1.f + expf(-(gg.z + bg[col + 2])))));
        vv.w = wmma::__float_to_tf32(vv.w * (2.f / (1.f + expf(-(gg.w + bg[col + 3])))));
        *(float4*)(Vc + t * ALD + c4) = vv;
        *(float4*)(vg + gi) = vv;
    }
    __syncthreads();

    if (tid < 64) {
        float s = 0.f;
        #pragma unroll 8
        for (int t = 0; t < 64; t++) s += Kc[t * ALD + tid];
        ksum[(((size_t)(b * HH + h)) * NC + c) * DK + tid] = s;
    }

    wmma::fragment<wmma::accumulator, 16, 16, 8, float> acc[2];
    wmma::fill_fragment(acc[0], 0.f);
    wmma::fill_fragment(acc[1], 0.f);
    #pragma unroll
    for (int kk = 0; kk < 64; kk += 8) {
        wmma::fragment<wmma::matrix_a, 16, 16, 8, wmma::precision::tf32, wmma::col_major> af;
        wmma::fragment<wmma::matrix_b, 16, 16, 8, wmma::precision::tf32, wmma::row_major> bf[2];
        wmma::load_matrix_sync(af, Kc + kk * ALD + wr * 16, ALD);
        wmma::load_matrix_sync(bf[0], Vc + kk * ALD + wc * 32, ALD);
        wmma::load_matrix_sync(bf[1], Vc + kk * ALD + wc * 32 + 16, ALD);
        wmma::mma_sync(acc[0], af, bf[0], acc[0]);
        wmma::mma_sync(acc[1], af, bf[1], acc[1]);
    }
    float* dst = ktv + (((size_t)(b * HH + h)) * NC + c) * 4096;
    wmma::store_matrix_sync(dst + (wr * 16) * 64 + wc * 32, acc[0], 64, wmma::mem_row_major);
    wmma::store_matrix_sync(dst + (wr * 16) * 64 + wc * 32 + 16, acc[1], 64, wmma::mem_row_major);
}

// ---------------------------------------------------------------------------
// Combined: blocks 0..511 = exclusive state prefix; blocks 512..1023 = inv.
// The two jobs are independent given ktv_k outputs and run concurrently.
// ---------------------------------------------------------------------------
#define DLD 68
__global__ __launch_bounds__(256) void state_inv_k(
    const float* __restrict__ ktv, float* __restrict__ st,
    const float* __restrict__ qf, const float* __restrict__ kf,
    const float* __restrict__ ksum, float* __restrict__ invd)
{
    __shared__ float Qc[64 * DLD];
    __shared__ float Kc[64 * DLD];
    __shared__ float base[64];
    const int tid = threadIdx.x;

    if (blockIdx.x < 512) {
        // ---- state prefix ----
        const int gid = blockIdx.x * 256 + tid;   // 0..131071
        const int bh = gid >> 12, e = gid & 4095;
        const size_t bs = ((size_t)bh * NC) * 4096 + e;
        float run = 0.f;
        #pragma unroll
        for (int c = 0; c < NC; c++) {
            st[bs + c * 4096] = wmma::__float_to_tf32(run);
            run += ktv[bs + c * 4096];
        }
        return;
    }

    // ---- inv ----
    const int bid = blockIdx.x - 512;             // 0..511
    const int tile = bid & 15, h = (bid >> 4) & 7, b = bid >> 7;
    const int bh = b * HH + h;
    const int t0 = tile * 64;

    if (tid < 64) {
        float s = 0.f;
        for (int c = 0; c < tile; c++) s += ksum[((size_t)bh * NC + c) * DK + tid];
        base[tid] = s;
    }
    for (int e = tid; e < 64 * 16; e += 256) {
        int r = e >> 4, c4 = (e & 15) * 4;
        size_t gi = ((size_t)(b * TT + t0 + r)) * PROJ + h * DK + c4;
        *(float4*)(Qc + r * DLD + c4) = *(const float4*)(qf + gi);
        *(float4*)(Kc + r * DLD + c4) = *(const float4*)(kf + gi);
    }
    __syncthreads();
    if (tid < 64) {
        float run = base[tid];
        #pragma unroll 8
        for (int r = 0; r < 64; r++) { run += Kc[r * DLD + tid]; Kc[r * DLD + tid] = run; }
    }
    __syncthreads();
    const int row = tid >> 2, seg = tid & 3;
    float d = 0.f;
    #pragma unroll
    for (int i = 0; i < 16; i++)
        d += Qc[row * DLD + seg * 16 + i] * Kc[row * DLD + seg * 16 + i];
    d += __shfl_xor_sync(0xffffffff, d, 1);
    d += __shfl_xor_sync(0xffffffff, d, 2);
    if (seg == 0) invd[(size_t)bh * TT + t0 + row] = 1.f / (d + 1e-6f);
}

// ---------------------------------------------------------------------------
// Attention, 128-row Q tiles. Per (b,h) pair (rb=pr, rb=7-pr): 18 tiles each.
// Q pre-scaled by inv. Upper half (chunk c0=2rb) uses state[c0]; lower half
// (chunk c1) uses state[c1]. Diagonal 128x128 block = two masked 64-steps;
// lower half at column c0 is a FULL tile (contribution already in state[c1]).
// ---------------------------------------------------------------------------
#define ATTN_SMEM ((128*ALD + 6*64*ALD + 128) * 4)   // 147968 B

__global__ __launch_bounds__(256) void attn_tc(
    const float* __restrict__ qf, const float* __restrict__ kf,
    const float* __restrict__ vg, const float* __restrict__ st,
    const float* __restrict__ invd,
    float* __restrict__ o, float* __restrict__ att)
{
    extern __shared__ float sm[];
    float* Qs  = sm;                               // 128 x ALD
    float* Kb[3] = { sm + 128*ALD, sm + 128*ALD + 64*ALD, sm + 128*ALD + 2*64*ALD };
    float* SV0 = sm + 128*ALD + 3*64*ALD;          // state[c0] then V[c0]
    float* SV1 = SV0 + 64*ALD;                     // state[c1] then V[c1]
    float* Ss  = SV1 + 64*ALD;                     // diag staging
    float* inv_s = Ss + 64*ALD;                    // 128

    const int tid = threadIdx.x;
    const int wid = tid >> 5, wr = wid >> 1, wc = wid & 1;   // 4x2 warps: 32x32 tiles
    const int pr = blockIdx.x, h = blockIdx.y, b = blockIdx.z;
    const int bh = b * HH + h;
    const size_t attBase = (size_t)bh * TT * TT;

    for (int half = 0; half < 2; half++) {
        const int rb = half ? (7 - pr) : pr;
        const int c0 = 2 * rb, c1 = 2 * rb + 1;
        const int t0 = rb * 128;

        // states -> SV0/SV1 (group 1)
        {
            const float* s0 = st + ((size_t)bh * NC + c0) * 4096;
            const float* s1 = st + ((size_t)bh * NC + c1) * 4096;
            #pragma unroll
            for (int p = 0; p < 4; p++) {
                int idx = tid + p * 256; int r = idx >> 4, s4 = (idx & 15) * 4;
                cp16(SV0 + r * ALD + s4, s0 + r * 64 + s4);
                cp16(SV1 + r * ALD + s4, s1 + r * 64 + s4);
            }
        }
        CP_COMMIT;
        if (tid < 128) inv_s[tid] = invd[(size_t)bh * TT + t0 + tid];
        __syncthreads();

        // Q (128x64) load + inv-scale + tf32
        #pragma unroll
        for (int p = 0; p < 8; p++) {
            int idx = tid + p * 256; int r = idx >> 4, c4 = (idx & 15) * 4;
            float4 q = *(const float4*)(qf + ((size_t)(b * TT + t0 + r)) * PROJ + h * DK + c4);
            float iv = inv_s[r];
            Qs[r * ALD + c4 + 0] = wmma::__float_to_tf32(q.x * iv);
            Qs[r * ALD + c4 + 1] = wmma::__float_to_tf32(q.y * iv);
            Qs[r * ALD + c4 + 2] = wmma::__float_to_tf32(q.z * iv);
            Qs[r * ALD + c4 + 3] = wmma::__float_to_tf32(q.w * iv);
        }
        // K(0) prefetch (group 2)
        #pragma unroll
        for (int p = 0; p < 4; p++) {
            int idx = tid + p * 256; int r = idx >> 4, s4 = (idx & 15) * 4;
            cp16(Kb[0] + r * ALD + s4, kf + ((size_t)(b * TT + r)) * PROJ + h * DK + s4);
        }
        CP_COMMIT;
        CP_WAIT1;          // states arrived
        __syncthreads();

        // acc_o = Q' @ state (upper warps state[c0], lower state[c1])
        wmma::fragment<wmma::accumulator, 16, 16, 8, float> acc_o[2][2];
        #pragma unroll
        for (int i = 0; i < 2; i++)
            #pragma unroll
            for (int j = 0; j < 2; j++) wmma::fill_fragment(acc_o[i][j], 0.f);
        {
            float* stw = (wr < 2) ? SV0 : SV1;
            #pragma unroll
            for (int kk = 0; kk < 64; kk += 8) {
                wmma::fragment<wmma::matrix_a, 16, 16, 8, wmma::precision::tf32, wmma::row_major> af[2];
                wmma::fragment<wmma::matrix_b, 16, 16, 8, wmma::precision::tf32, wmma::row_major> bf[2];
                #pragma unroll
                for (int i = 0; i < 2; i++)
                    wmma::load_matrix_sync(af[i], Qs + (wr * 32 + i * 16) * ALD + kk, ALD);
                #pragma unroll
                for (int j = 0; j < 2; j++)
                    wmma::load_matrix_sync(bf[j], stw + kk * ALD + wc * 32 + j * 16, ALD);
                #pragma unroll
                for (int i = 0; i < 2; i++)
                    #pragma unroll
                    for (int j = 0; j < 2; j++)
                        wmma::mma_sync(acc_o[i][j], af[i], bf[j], acc_o[i][j]);
            }
        }
        __syncthreads();   // state reads done; SV0/SV1 reusable for V

        for (int jt = 0; jt <= c1; jt++) {
            // issue exactly one cp.async group per iteration
            if (jt < c0) {
                float* dst = Kb[(jt + 1) % 3];
                const float* src = kf + ((size_t)(b * TT + (jt + 1) * 64)) * PROJ + h * DK;
                #pragma unroll
                for (int p = 0; p < 4; p++) {
                    int idx = tid + p * 256; int r = idx >> 4, s4 = (idx & 15) * 4;
                    cp16(dst + r * ALD + s4, src + (size_t)r * PROJ + s4);
                }
            } else if (jt == c0) {
                float* dst = Kb[c1 % 3];
                const float* srcK = kf + ((size_t)(b * TT + c1 * 64)) * PROJ + h * DK;
                const float* srcV = vg + ((size_t)(b * TT + t0)) * PROJ + h * DV;
                #pragma unroll
                for (int p = 0; p < 4; p++) {
                    int idx = tid + p * 256; int r = idx >> 4, s4 = (idx & 15) * 4;
                    cp16(dst + r * ALD + s4, srcK + (size_t)r * PROJ + s4);
                    cp16(SV0 + r * ALD + s4, srcV + (size_t)r * PROJ + s4);
                }
            } else { // jt == c1: V1
                const float* srcV = vg + ((size_t)(b * TT + t0 + 64)) * PROJ + h * DV;
                #pragma unroll
                for (int p = 0; p < 4; p++) {
                    int idx = tid + p * 256; int r = idx >> 4, s4 = (idx & 15) * 4;
                    cp16(SV1 + r * ALD + s4, srcV + (size_t)r * PROJ + s4);
                }
            }
            CP_COMMIT;
            CP_WAIT1;      // current K tile arrived
            __syncthreads();

            float* Kc = Kb[jt % 3];

            if (jt < c1) {
                // S (128x64) = Q' @ K^T : warp 32x32, 4 frags
                wmma::fragment<wmma::accumulator, 16, 16, 8, float> acc_s[2][2];
                #pragma unroll
                for (int i = 0; i < 2; i++)
                    #pragma unroll
                    for (int j = 0; j < 2; j++) wmma::fill_fragment(acc_s[i][j], 0.f);
                #pragma unroll
                for (int kk = 0; kk < 64; kk += 8) {
                    wmma::fragment<wmma::matrix_a, 16, 16, 8, wmma::precision::tf32, wmma::row_major> af[2];
                    wmma::fragment<wmma::matrix_b, 16, 16, 8, wmma::precision::tf32, wmma::col_major> bf[2];
                    #pragma unroll
                    for (int i = 0; i < 2; i++)
                        wmma::load_matrix_sync(af[i], Qs + (wr * 32 + i * 16) * ALD + kk, ALD);
                    #pragma unroll
                    for (int j = 0; j < 2; j++)
                        wmma::load_matrix_sync(bf[j], Kc + (wc * 32 + j * 16) * ALD + kk, ALD);
                    #pragma unroll
                    for (int i = 0; i < 2; i++)
                        #pragma unroll
                        for (int j = 0; j < 2; j++)
                            wmma::mma_sync(acc_s[i][j], af[i], bf[j], acc_s[i][j]);
                }

                if (jt < c0 || wr >= 2) {
                    // full rows: S is final att — store frags direct
                    #pragma unroll
                    for (int i = 0; i < 2; i++)
                        #pragma unroll
                        for (int j = 0; j < 2; j++)
                            wmma::store_matrix_sync(
                                att + attBase + (size_t)(t0 + wr * 32 + i * 16) * TT
                                    + jt * 64 + wc * 32 + j * 16,
                                acc_s[i][j], TT, wmma::mem_row_major);
                } else {
                    // upper-diag rows (jt==c0, wr<2): stage to Ss
                    #pragma unroll
                    for (int i = 0; i < 2; i++)
                        #pragma unroll
                        for (int j = 0; j < 2; j++)
                            wmma::store_matrix_sync(
                                Ss + (wr * 32 + i * 16) * ALD + wc * 32 + j * 16,
                                acc_s[i][j], ALD, wmma::mem_row_major);
                }

                if (jt == c0) {
                    // diagonal (upper 64 rows): mask, att write, tf32, S@V0
                    CP_WAIT0;          // K(c1) + V0 arrived
                    __syncthreads();
                    for (int e = tid; e < 64 * 16; e += 256) {
                        int r = e >> 4, c4 = (e & 15) * 4;
                        float4 s = *(float4*)(Ss + r * ALD + c4);
                        if (c4 + 0 > r) s.x = 0.f;
                        if (c4 + 1 > r) s.y = 0.f;
                        if (c4 + 2 > r) s.z = 0.f;
                        if (c4 + 3 > r) s.w = 0.f;
                        *(float4*)(att + attBase + (size_t)(t0 + r) * TT + t0 + c4) = s;
                        Ss[r * ALD + c4 + 0] = wmma::__float_to_tf32(s.x);
                        Ss[r * ALD + c4 + 1] = wmma::__float_to_tf32(s.y);
                        Ss[r * ALD + c4 + 2] = wmma::__float_to_tf32(s.z);
                        Ss[r * ALD + c4 + 3] = wmma::__float_to_tf32(s.w);
                    }
                    __syncthreads();
                    if (wr < 2) {
                        #pragma unroll
                        for (int kk = 0; kk < 64; kk += 8) {
                            wmma::fragment<wmma::matrix_a, 16, 16, 8, wmma::precision::tf32, wmma::row_major> af[2];
                            wmma::fragment<wmma::matrix_b, 16, 16, 8, wmma::precision::tf32, wmma::row_major> bf[2];
                            #pragma unroll
                            for (int i = 0; i < 2; i++)
                                wmma::load_matrix_sync(af[i], Ss + (wr * 32 + i * 16) * ALD + kk, ALD);
                            #pragma unroll
                            for (int j = 0; j < 2; j++)
                                wmma::load_matrix_sync(bf[j], SV0 + kk * ALD + wc * 32 + j * 16, ALD);
                            #pragma unroll
                            for (int i = 0; i < 2; i++)
                                #pragma unroll
                                for (int j = 0; j < 2; j++)
                                    wmma::mma_sync(acc_o[i][j], af[i], bf[j], acc_o[i][j]);
                        }
                    }
                }
            } else {
                // jt == c1: lower-diag 64x64 (rows t0+64..t0+127), lower warps only
                if (wr >= 2) {
                    wmma::fragment<wmma::accumulator, 16, 16, 8, float> acc_s[2][2];
                    #pragma unroll
                    for (int i = 0; i < 2; i++)
                        #pragma unroll
                        for (int j = 0; j < 2; j++) wmma::fill_fragment(acc_s[i][j], 0.f);
                    const int lr = (wr - 2) * 32;   // local row band in 64-row tile
                    #pragma unroll
                    for (int kk = 0; kk < 64; kk += 8) {
                        wmma::fragment<wmma::matrix_a, 16, 16, 8, wmma::precision::tf32, wmma::row_major> af[2];
                        wmma::fragment<wmma::matrix_b, 16, 16, 8, wmma::precision::tf32, wmma::col_major> bf[2];
                        #pragma unroll
                        for (int i = 0; i < 2; i++)
                            wmma::load_matrix_sync(af[i], Qs + (64 + lr + i * 16) * ALD + kk, ALD);
                        #pragma unroll
                        for (int j = 0; j < 2; j++)
                            wmma::load_matrix_sync(bf[j], Kc + (wc * 32 + j * 16) * ALD + kk, ALD);
                        #pragma unroll
                        for (int i = 0; i < 2; i++)
                            #pragma unroll
                            for (int j = 0; j < 2; j++)
                                wmma::mma_sync(acc_s[i][j], af[i], bf[j], acc_s[i][j]);
                    }
                    #pragma unroll
                    for (int i = 0; i < 2; i++)
                        #pragma unroll
                        for (int j = 0; j < 2; j++)
                            wmma::store_matrix_sync(
                                Ss + (lr + i * 16) * ALD + wc * 32 + j * 16,
                                acc_s[i][j], ALD, wmma::mem_row_major);
                }
                CP_WAIT0;          // V1 arrived
                __syncthreads();
                for (int e = tid; e < 64 * 16; e += 256) {
                    int r = e >> 4, c4 = (e & 15) * 4;
                    float4 s = *(float4*)(Ss + r * ALD + c4);
                    if (c4 + 0 > r) s.x = 0.f;
                    if (c4 + 1 > r) s.y = 0.f;
                    if (c4 + 2 > r) s.z = 0.f;
                    if (c4 + 3 > r) s.w = 0.f;
                    *(float4*)(att + attBase + (size_t)(t0 + 64 + r) * TT + t0 + 64 + c4) = s;
                    Ss[r * ALD + c4 + 0] = wmma::__float_to_tf32(s.x);
                    Ss[r * ALD + c4 + 1] = wmma::__float_to_tf32(s.y);
                    Ss[r * ALD + c4 + 2] = wmma::__float_to_tf32(s.z);
                    Ss[r * ALD + c4 + 3] = wmma::__float_to_tf32(s.w);
                }
                __syncthreads();
                if (wr >= 2) {
                    const int lr = (wr - 2) * 32;
                    #pragma unroll
                    for (int kk = 0; kk < 64; kk += 8) {
                        wmma::fragment<wmma::matrix_a, 16, 16, 8, wmma::precision::tf32, wmma::row_major> af[2];
                        wmma::fragment<wmma::matrix_b, 16, 16, 8, wmma::precision::tf32, wmma::row_major> bf[2];
                        #pragma unroll
                        for (int i = 0; i < 2; i++)
                            wmma::load_matrix_sync(af[i], Ss + (lr + i * 16) * ALD + kk, ALD);
                        #pragma unroll
                        for (int j = 0; j < 2; j++)
                            wmma::load_matrix_sync(bf[j], SV1 + kk * ALD + wc * 32 + j * 16, ALD);
                        #pragma unroll
                        for (int i = 0; i < 2; i++)
                            #pragma unroll
                            for (int j = 0; j < 2; j++)
                                wmma::mma_sync(acc_o[i][j], af[i], bf[j], acc_o[i][j]);
                    }
                }
            }
        }

        // O store (raw fp32 frags; out-proj rounds its own A)
        #pragma unroll
        for (int i = 0; i < 2; i++)
            #pragma unroll
            for (int j = 0; j < 2; j++)
                wmma::store_matrix_sync(
                    o + ((size_t)(b * TT + t0 + wr * 32 + i * 16)) * PROJ
                        + h * DV + wc * 32 + j * 16,
                    acc_o[i][j], PROJ, wmma::mem_row_major);

        // zero-fill strictly-upper tiles
        const float4 z = { 0.f, 0.f, 0.f, 0.f };
        for (int jt = c0 + 1; jt < NC; jt++)
            for (int e = tid; e < 64 * 16; e += 256) {
                int r = e >> 4, c4 = (e & 15) * 4;
                *(float4*)(att + attBase + (size_t)(t0 + r) * TT + jt * 64 + c4) = z;
            }
        for (int jt = c1 + 1; jt < NC; jt++)
            for (int e = tid; e < 64 * 16; e += 256) {
                int r = e >> 4, c4 = (e & 15) * 4;
                *(float4*)(att + attBase + (size_t)(t0 + 64 + r) * TT + jt * 64 + c4) = z;
            }
        __syncthreads();   // smem reuse barrier for next half
    }
}

// ---------------------------------------------------------------------------
extern "C" void kernel_launch(void* const* d_in, const int* in_sizes, int n_in,
                              void* d_out, int out_size)
{
    const float* query = (const float*)d_in[0];
    const float* key   = (const float*)d_in[1];
    const float* value = (const float*)d_in[2];
    const float* Wq    = (const float*)d_in[3];
    const float* Wk    = (const float*)d_in[4];
    const float* Wv    = (const float*)d_in[5];
    const float* Wg    = (const float*)d_in[6];
    const float* bg    = (const float*)d_in[7];
    const float* Wo    = (const float*)d_in[8];

    float* out = (float*)d_out;                 // [B,T,M]
    float* att = out + (size_t)NTOK * MM;       // [B,H,T,T]

    float *w, *qf, *kf, *vg, *gt, *ov, *ktv, *st, *ksum, *invd;
    cudaGetSymbolAddress((void**)&w,  g_w);
    cudaGetSymbolAddress((void**)&qf, g_qf);
    cudaGetSymbolAddress((void**)&kf, g_kf);
    cudaGetSymbolAddress((void**)&vg, g_v);
    cudaGetSymbolAddress((void**)&gt, g_gt);
    cudaGetSymbolAddress((void**)&ov, g_o);
    cudaGetSymbolAddress((void**)&ktv, g_ktv);
    cudaGetSymbolAddress((void**)&st, g_state);
    cudaGetSymbolAddress((void**)&ksum, g_ksum);
    cudaGetSymbolAddress((void**)&invd, g_inv);

    cudaFuncSetAttribute(gemm128, cudaFuncAttributeMaxDynamicSharedMemorySize, GSM);
    cudaFuncSetAttribute(attn_tc, cudaFuncAttributeMaxDynamicSharedMemorySize, ATTN_SMEM);

    dim3 bb(256);

    // Round weights to tf32
    WArgs wa; wa.in[0] = Wq; wa.in[1] = Wk; wa.in[2] = Wv; wa.in[3] = Wg; wa.in[4] = Wo;
    preround_w<<<dim3(256, 1, 5), bb>>>(wa, w);

    // Batched Q/K/V/gate projections (A conversion folded into GEMM)
    GemmArgs p;
    p.A[0] = query; p.W[0] = w;            p.C[0] = qf; p.mode[0] = MODE_PHI;
    p.A[1] = key;   p.W[1] = w + 262144;   p.C[1] = kf; p.mode[1] = MODE_PHI;
    p.A[2] = value; p.W[2] = w + 2*262144; p.C[2] = vg; p.mode[2] = MODE_RAW;
    p.A[3] = value; p.W[3] = w + 3*262144; p.C[3] = gt; p.mode[3] = MODE_RAW;
    gemm128<<<dim3(4, 32, 4), bb, GSM>>>(p);

    // Fused gate + per-chunk K^T V + k sums
    ktv_k<<<dim3(NC, HH, BB), bb>>>(kf, vg, gt, bg, ktv, ksum);

    // State prefix + inv denominators (one launch, concurrent)
    state_inv_k<<<1024, bb>>>(ktv, st, qf, kf, ksum, invd);

    // Attention: 128-row tiles, paired row-blocks (rb, 7-rb)
    attn_tc<<<dim3(4, HH, BB), bb, ATTN_SMEM>>>(qf, kf, vg, st, invd, ov, att);

    // Output projection
    GemmArgs po;
    po.A[0] = ov; po.W[0] = w + 4*262144; po.C[0] = out; po.mode[0] = MODE_RAW;
    po.A[1] = po.A[2] = po.A[3] = ov; po.W[1] = po.W[2] = po.W[3] = po.W[0];
    po.C[1] = po.C[2] = po.C[3] = out; po.mode[1] = po.mode[2] = po.mode[3] = MODE_RAW;
    gemm128<<<dim3(4, 32, 1), bb, GSM>>>(po);
}